// round 1
// baseline (speedup 1.0000x reference)
#include <cuda_runtime.h>
#include <math.h>

#define Lc 26
#define Tc 512
#define Dc 768
#define NHc 12
#define NGc 4
#define GSc 3
#define HDc 64
#define FFc 2048
#define CACHEc 1536
#define Sc 2048
#define Vocab 32000
#define WINc 512
#define QKVW 1280  /* (NH + 2*NG)*HD */

// ---------------- scratch (device globals; allocation-free) ----------------
__device__ float g_h[Tc * Dc];
__device__ float g_x[Tc * Dc];
__device__ float g_qkv[Tc * QKVW];
__device__ float g_q[NHc * Tc * HDc];      // [h][t][d]
__device__ float g_kf[NGc * Sc * HDc];     // [g][s][d]
__device__ float g_vf[NGc * HDc * Sc];     // [g][d][s]
__device__ float g_sc[NHc * Tc * Sc];      // [h][t][s]  (50 MB)
__device__ float g_attn[Tc * NHc * HDc];   // [t][h*64+d]
__device__ float g_t1[Tc * Dc];
__device__ float g_gate[Tc * FFc];
__device__ float g_up[Tc * FFc];

// ---------------- helpers ----------------
__device__ __forceinline__ float blockReduceSum(float v) {
    __shared__ float sh[8];
    __syncthreads();
    int lane = threadIdx.x & 31, w = threadIdx.x >> 5;
#pragma unroll
    for (int o = 16; o; o >>= 1) v += __shfl_down_sync(0xffffffffu, v, o);
    if (lane == 0) sh[w] = v;
    __syncthreads();
    int nw = blockDim.x >> 5;
    if (w == 0) {
        v = (lane < nw) ? sh[lane] : 0.f;
#pragma unroll
        for (int o = 4; o; o >>= 1) v += __shfl_down_sync(0xffffffffu, v, o);
        if (lane == 0) sh[0] = v;
    }
    __syncthreads();
    return sh[0];
}

__device__ __forceinline__ float blockReduceMax(float v) {
    __shared__ float sh[8];
    __syncthreads();
    int lane = threadIdx.x & 31, w = threadIdx.x >> 5;
#pragma unroll
    for (int o = 16; o; o >>= 1) v = fmaxf(v, __shfl_down_sync(0xffffffffu, v, o));
    if (lane == 0) sh[w] = v;
    __syncthreads();
    int nw = blockDim.x >> 5;
    if (w == 0) {
        v = (lane < nw) ? sh[lane] : -3.4e38f;
#pragma unroll
        for (int o = 4; o; o >>= 1) v = fmaxf(v, __shfl_down_sync(0xffffffffu, v, o));
        if (lane == 0) sh[0] = v;
    }
    __syncthreads();
    return sh[0];
}

// ---------------- elementwise kernels ----------------
__global__ void k_copy(float* __restrict__ dst, const float* __restrict__ src, int n) {
    int i = blockIdx.x * blockDim.x + threadIdx.x;
    if (i < n) dst[i] = src[i];
}

__global__ void k_rmsnorm(const float* __restrict__ in, const float* __restrict__ w,
                          float* __restrict__ out) {
    int row = blockIdx.x;
    const float* x = in + row * Dc;
    float ss = 0.f;
    for (int d = threadIdx.x; d < Dc; d += blockDim.x) { float v = x[d]; ss += v * v; }
    float tot = blockReduceSum(ss);
    float rs = rsqrtf(tot / (float)Dc + 1e-6f);
    for (int d = threadIdx.x; d < Dc; d += blockDim.x)
        out[row * Dc + d] = x[d] * rs * (1.f + w[d]);
}

// h[row] += rmsnorm(in[row], w)
__global__ void k_add_rmsnorm(float* __restrict__ h, const float* __restrict__ in,
                              const float* __restrict__ w) {
    int row = blockIdx.x;
    const float* x = in + row * Dc;
    float ss = 0.f;
    for (int d = threadIdx.x; d < Dc; d += blockDim.x) { float v = x[d]; ss += v * v; }
    float tot = blockReduceSum(ss);
    float rs = rsqrtf(tot / (float)Dc + 1e-6f);
    for (int d = threadIdx.x; d < Dc; d += blockDim.x)
        h[row * Dc + d] += x[d] * rs * (1.f + w[d]);
}

__global__ void k_gelumul(float* __restrict__ g, const float* __restrict__ u, int n) {
    int i = blockIdx.x * blockDim.x + threadIdx.x;
    if (i < n) {
        float x = g[i];
        float t = tanhf(0.7978845608028654f * (x + 0.044715f * x * x * x));
        g[i] = 0.5f * x * (1.f + t) * u[i];
    }
}

// ---------------- cache copies ----------------
__global__ void k_copy_kcache(const float* __restrict__ src, float* __restrict__ kf) {
    int i = blockIdx.x * blockDim.x + threadIdx.x;  // NG*CACHE*HD
    if (i >= NGc * CACHEc * HDc) return;
    int g = i / (CACHEc * HDc);
    int r = i - g * (CACHEc * HDc);
    kf[g * Sc * HDc + r] = src[i];
}

__global__ void k_copy_vcache(const float* __restrict__ src, float* __restrict__ vf) {
    int i = blockIdx.x * blockDim.x + threadIdx.x;  // NG*HD*CACHE
    if (i >= NGc * HDc * CACHEc) return;
    int g = i / (HDc * CACHEc);
    int r = i - g * (HDc * CACHEc);
    int d = r / CACHEc;
    int s = r - d * CACHEc;
    vf[(g * HDc + d) * Sc + s] = src[i];
}

// ---------------- qkv split: head rmsnorm + rope + cache append ----------------
__global__ void k_qkprep(const float* __restrict__ qkv,
                         const float* __restrict__ qw, const float* __restrict__ kw,
                         const float* __restrict__ cos_, const float* __restrict__ sin_,
                         float* __restrict__ qout, float* __restrict__ kf,
                         float* __restrict__ vf) {
    int t = blockIdx.x, g = blockIdx.y, d = threadIdx.x;  // 64 threads
    const float* base = qkv + ((t * NGc + g) * (GSc + 2)) * HDc;
    __shared__ float sh[HDc];
    __shared__ float r2[2];
    float c = cos_[t * HDc + d], s = sin_[t * HDc + d];
#pragma unroll
    for (int j = 0; j <= GSc; j++) {
        float v = base[j * HDc + d];
        float sq = v * v;
#pragma unroll
        for (int o = 16; o; o >>= 1) sq += __shfl_down_sync(0xffffffffu, sq, o);
        if ((d & 31) == 0) r2[d >> 5] = sq;
        __syncthreads();
        float tot = r2[0] + r2[1];
        float rs = rsqrtf(tot * (1.f / (float)HDc) + 1e-6f);
        const float* wgt = (j < GSc) ? qw : kw;
        float nv = v * rs * (1.f + wgt[d]);
        sh[d] = nv;
        __syncthreads();
        float rot = (d < 32) ? -sh[d + 32] : sh[d - 32];
        float outv = nv * c + rot * s;
        if (j < GSc) qout[((g * GSc + j) * Tc + t) * HDc + d] = outv;
        else kf[(g * Sc + CACHEc + t) * HDc + d] = outv;
        __syncthreads();
    }
    vf[(g * HDc + d) * Sc + CACHEc + t] = base[(GSc + 2 - 1) * HDc + d];
}

// ---------------- scores: QK^T fused softcap + analytic mask ----------------
__global__ void __launch_bounds__(256) k_scores(const float* __restrict__ q,
                                                const float* __restrict__ kf,
                                                float* __restrict__ sc, int is_local) {
    int h = blockIdx.z, g = h / GSc;
    int t0 = blockIdx.y * 64, s0 = blockIdx.x * 64;
    __shared__ float Qs[64][65];
    __shared__ float Ks[64][65];
    const float* Q = q + h * Tc * HDc;
    const float* K = kf + g * Sc * HDc;
    for (int e = threadIdx.x; e < 64 * 64; e += 256) {
        int r = e >> 6, d = e & 63;
        Qs[d][r] = Q[(t0 + r) * 64 + d];
        Ks[d][r] = K[(s0 + r) * 64 + d];
    }
    __syncthreads();
    int tx = threadIdx.x & 15, ty = threadIdx.x >> 4;
    float acc[4][4] = {};
#pragma unroll 16
    for (int kk = 0; kk < 64; kk++) {
        float a0 = Qs[kk][ty * 4 + 0], a1 = Qs[kk][ty * 4 + 1];
        float a2 = Qs[kk][ty * 4 + 2], a3 = Qs[kk][ty * 4 + 3];
        float b0 = Ks[kk][tx * 4 + 0], b1 = Ks[kk][tx * 4 + 1];
        float b2 = Ks[kk][tx * 4 + 2], b3 = Ks[kk][tx * 4 + 3];
        acc[0][0] += a0 * b0; acc[0][1] += a0 * b1; acc[0][2] += a0 * b2; acc[0][3] += a0 * b3;
        acc[1][0] += a1 * b0; acc[1][1] += a1 * b1; acc[1][2] += a1 * b2; acc[1][3] += a1 * b3;
        acc[2][0] += a2 * b0; acc[2][1] += a2 * b1; acc[2][2] += a2 * b2; acc[2][3] += a2 * b3;
        acc[3][0] += a3 * b0; acc[3][1] += a3 * b1; acc[3][2] += a3 * b2; acc[3][3] += a3 * b3;
    }
    const float scale = 0.125f;  // 1/sqrt(64)
#pragma unroll
    for (int i = 0; i < 4; i++) {
#pragma unroll
        for (int j = 0; j < 4; j++) {
            int t = t0 + ty * 4 + i, sp = s0 + tx * 4 + j;
            float v = tanhf(acc[i][j] * scale * 0.02f) * 50.f;
            int qpos = CACHEc + t;
            bool ok = (sp <= qpos) && (!is_local || sp > qpos - WINc);
            sc[(h * Tc + t) * Sc + sp] = ok ? v : v - 1e9f;
        }
    }
}

// ---------------- softmax over rows of length S ----------------
__global__ void k_softmax(float* __restrict__ sc) {
    float* r = sc + (size_t)blockIdx.x * Sc;
    float m = -3.4e38f;
    for (int i = threadIdx.x; i < Sc; i += blockDim.x) m = fmaxf(m, r[i]);
    m = blockReduceMax(m);
    float sum = 0.f;
    for (int i = threadIdx.x; i < Sc; i += blockDim.x) {
        float e = __expf(r[i] - m);
        r[i] = e;
        sum += e;
    }
    sum = blockReduceSum(sum);
    float inv = 1.f / sum;
    for (int i = threadIdx.x; i < Sc; i += blockDim.x) r[i] *= inv;
}

// ---------------- attn = probs @ V^T ----------------
__global__ void __launch_bounds__(256) k_attnv(const float* __restrict__ sc,
                                               const float* __restrict__ vf,
                                               float* __restrict__ attn) {
    int h = blockIdx.y, g = h / GSc;
    int t0 = blockIdx.x * 64;
    const float* P = sc + (size_t)h * Tc * Sc;
    const float* Vv = vf + g * HDc * Sc;
    __shared__ float Ps[32][65];
    __shared__ float Vs[32][65];
    int tx = threadIdx.x & 15, ty = threadIdx.x >> 4;
    float acc[4][4] = {};
    for (int s0 = 0; s0 < Sc; s0 += 32) {
        for (int e = threadIdx.x; e < 64 * 32; e += 256) {
            int r = e >> 5, ss = e & 31;
            Ps[ss][r] = P[(size_t)(t0 + r) * Sc + s0 + ss];
            Vs[ss][r] = Vv[(size_t)r * Sc + s0 + ss];
        }
        __syncthreads();
#pragma unroll
        for (int kk = 0; kk < 32; kk++) {
            float a0 = Ps[kk][ty * 4 + 0], a1 = Ps[kk][ty * 4 + 1];
            float a2 = Ps[kk][ty * 4 + 2], a3 = Ps[kk][ty * 4 + 3];
            float b0 = Vs[kk][tx * 4 + 0], b1 = Vs[kk][tx * 4 + 1];
            float b2 = Vs[kk][tx * 4 + 2], b3 = Vs[kk][tx * 4 + 3];
            acc[0][0] += a0 * b0; acc[0][1] += a0 * b1; acc[0][2] += a0 * b2; acc[0][3] += a0 * b3;
            acc[1][0] += a1 * b0; acc[1][1] += a1 * b1; acc[1][2] += a1 * b2; acc[1][3] += a1 * b3;
            acc[2][0] += a2 * b0; acc[2][1] += a2 * b1; acc[2][2] += a2 * b2; acc[2][3] += a2 * b3;
            acc[3][0] += a3 * b0; acc[3][1] += a3 * b1; acc[3][2] += a3 * b2; acc[3][3] += a3 * b3;
        }
        __syncthreads();
    }
#pragma unroll
    for (int i = 0; i < 4; i++)
#pragma unroll
        for (int j = 0; j < 4; j++)
            attn[(t0 + ty * 4 + i) * (NHc * HDc) + h * HDc + tx * 4 + j] = acc[i][j];
}

// ---------------- generic SGEMM: C[M,N] = A[M,K] @ B[K,N] (row-major) -------
// M,N multiples of 64; K multiple of 16.
__global__ void __launch_bounds__(256) k_sgemm(const float* __restrict__ A,
                                               const float* __restrict__ B,
                                               float* __restrict__ C,
                                               int M, int N, int K) {
    __shared__ float As[16][64];
    __shared__ float Bs[16][64];
    int bm = blockIdx.y * 64, bn = blockIdx.x * 64;
    int tid = threadIdx.x;
    int tx = tid & 15, ty = tid >> 4;
    int arow = tid >> 2, ac = (tid & 3) << 2;
    int brow = tid >> 4, bc = (tid & 15) << 2;
    float acc[4][4] = {};
    for (int k0 = 0; k0 < K; k0 += 16) {
        float4 av = *(const float4*)(A + (size_t)(bm + arow) * K + k0 + ac);
        As[ac + 0][arow] = av.x;
        As[ac + 1][arow] = av.y;
        As[ac + 2][arow] = av.z;
        As[ac + 3][arow] = av.w;
        *(float4*)&Bs[brow][bc] = *(const float4*)(B + (size_t)(k0 + brow) * N + bn + bc);
        __syncthreads();
#pragma unroll
        for (int kk = 0; kk < 16; kk++) {
            float4 a = *(const float4*)&As[kk][ty << 2];
            float4 b = *(const float4*)&Bs[kk][tx << 2];
            acc[0][0] += a.x * b.x; acc[0][1] += a.x * b.y; acc[0][2] += a.x * b.z; acc[0][3] += a.x * b.w;
            acc[1][0] += a.y * b.x; acc[1][1] += a.y * b.y; acc[1][2] += a.y * b.z; acc[1][3] += a.y * b.w;
            acc[2][0] += a.z * b.x; acc[2][1] += a.z * b.y; acc[2][2] += a.z * b.z; acc[2][3] += a.z * b.w;
            acc[3][0] += a.w * b.x; acc[3][1] += a.w * b.y; acc[3][2] += a.w * b.z; acc[3][3] += a.w * b.w;
        }
        __syncthreads();
    }
#pragma unroll
    for (int i = 0; i < 4; i++) {
        float4 o = make_float4(acc[i][0], acc[i][1], acc[i][2], acc[i][3]);
        *(float4*)(C + (size_t)(bm + (ty << 2) + i) * N + bn + (tx << 2)) = o;
    }
}

// ---------------- host ----------------
extern "C" void kernel_launch(void* const* d_in, const int* in_sizes, int n_in,
                              void* d_out, int out_size) {
    const float *embeddings = 0, *kvk = 0, *kvv = 0, *pre_attn = 0, *wqkv = 0,
                *qnorm = 0, *knorm = 0, *wout = 0, *post_attn = 0, *pre_ff = 0,
                *wgate = 0, *wup = 0, *wdown = 0, *post_ff = 0, *finalw = 0,
                *wlm = 0, *cosg = 0, *sing = 0, *cosl = 0, *sinl = 0;
    int kv_n = 0, n19968 = 0, n1664 = 0, n40 = 0, n32k = 0;
    for (int i = 0; i < n_in; i++) {
        const float* p = (const float*)d_in[i];
        int s = in_sizes[i];
        if (s == 393216) embeddings = p;
        else if (s == 10223616) { if (kv_n++ == 0) kvk = p; else kvv = p; }
        else if (s == 19968) {
            if (n19968 == 0) pre_attn = p;
            else if (n19968 == 1) post_attn = p;
            else if (n19968 == 2) pre_ff = p;
            else post_ff = p;
            n19968++;
        }
        else if (s == 25559040) wqkv = p;
        else if (s == 1664) { if (n1664++ == 0) qnorm = p; else knorm = p; }
        else if (s == 15335424) wout = p;
        else if (s == 40894464) {
            if (n40 == 0) wgate = p;
            else if (n40 == 1) wup = p;
            else wdown = p;
            n40++;
        }
        else if (s == 768) finalw = p;
        else if (s == 24576000) wlm = p;
        else if (s == 32768) {
            if (n32k == 0) cosg = p;
            else if (n32k == 1) sing = p;
            else if (n32k == 2) cosl = p;
            else sinl = p;
            n32k++;
        }
        // 1048576 = masks: computed analytically, not read
    }

    float *ph, *px, *pqkv, *pq, *pkf, *pvf, *psc, *pattn, *pt1, *pgate, *pup;
    cudaGetSymbolAddress((void**)&ph, g_h);
    cudaGetSymbolAddress((void**)&px, g_x);
    cudaGetSymbolAddress((void**)&pqkv, g_qkv);
    cudaGetSymbolAddress((void**)&pq, g_q);
    cudaGetSymbolAddress((void**)&pkf, g_kf);
    cudaGetSymbolAddress((void**)&pvf, g_vf);
    cudaGetSymbolAddress((void**)&psc, g_sc);
    cudaGetSymbolAddress((void**)&pattn, g_attn);
    cudaGetSymbolAddress((void**)&pt1, g_t1);
    cudaGetSymbolAddress((void**)&pgate, g_gate);
    cudaGetSymbolAddress((void**)&pup, g_up);

    // h = embeddings
    k_copy<<<(Tc * Dc + 255) / 256, 256>>>(ph, embeddings, Tc * Dc);

    for (int i = 0; i < Lc; i++) {
        int is_local = ((i + 1) % 6 == 0) ? 1 : 0;
        const float* cs = is_local ? cosl : cosg;
        const float* sn = is_local ? sinl : sing;

        // KV cache -> working buffers
        k_copy_kcache<<<(NGc * CACHEc * HDc + 255) / 256, 256>>>(
            kvk + (size_t)i * NGc * CACHEc * HDc, pkf);
        k_copy_vcache<<<(NGc * HDc * CACHEc + 255) / 256, 256>>>(
            kvv + (size_t)i * NGc * HDc * CACHEc, pvf);

        // pre-attn norm
        k_rmsnorm<<<Tc, 256>>>(ph, pre_attn + i * Dc, px);
        // qkv projection
        k_sgemm<<<dim3(QKVW / 64, Tc / 64), 256>>>(px, wqkv + (size_t)i * Dc * QKVW,
                                                   pqkv, Tc, QKVW, Dc);
        // per-head norm + rope + cache append
        k_qkprep<<<dim3(Tc, NGc), HDc>>>(pqkv, qnorm + i * HDc, knorm + i * HDc,
                                         cs, sn, pq, pkf, pvf);
        // scores + softcap + mask
        k_scores<<<dim3(Sc / 64, Tc / 64, NHc), 256>>>(pq, pkf, psc, is_local);
        // softmax
        k_softmax<<<NHc * Tc, 256>>>(psc);
        // attn = P @ V^T
        k_attnv<<<dim3(Tc / 64, NHc), 256>>>(psc, pvf, pattn);
        // output projection
        k_sgemm<<<dim3(Dc / 64, Tc / 64), 256>>>(pattn, wout + (size_t)i * Dc * Dc,
                                                 pt1, Tc, Dc, NHc * HDc);
        // h += rmsnorm(o)
        k_add_rmsnorm<<<Tc, 256>>>(ph, pt1, post_attn + i * Dc);

        // FF
        k_rmsnorm<<<Tc, 256>>>(ph, pre_ff + i * Dc, px);
        k_sgemm<<<dim3(FFc / 64, Tc / 64), 256>>>(px, wgate + (size_t)i * Dc * FFc,
                                                  pgate, Tc, FFc, Dc);
        k_sgemm<<<dim3(FFc / 64, Tc / 64), 256>>>(px, wup + (size_t)i * Dc * FFc,
                                                  pup, Tc, FFc, Dc);
        k_gelumul<<<(Tc * FFc + 255) / 256, 256>>>(pgate, pup, Tc * FFc);
        k_sgemm<<<dim3(Dc / 64, Tc / 64), 256>>>(pgate, wdown + (size_t)i * FFc * Dc,
                                                 pt1, Tc, Dc, FFc);
        k_add_rmsnorm<<<Tc, 256>>>(ph, pt1, post_ff + i * Dc);
    }

    // final norm + LM head
    k_rmsnorm<<<Tc, 256>>>(ph, finalw, px);
    k_sgemm<<<dim3(Vocab / 64, Tc / 64), 256>>>(px, wlm, (float*)d_out, Tc, Vocab, Dc);
}

// round 2
// speedup vs baseline: 1.2084x; 1.2084x over previous
#include <cuda_runtime.h>
#include <math.h>
#include <stdint.h>

#define Lc 26
#define Tc 512
#define Dc 768
#define NHc 12
#define NGc 4
#define GSc 3
#define HDc 64
#define FFc 2048
#define CACHEc 1536
#define Sc 2048
#define Vocab 32000
#define WINc 512
#define QKVW 1280  /* (NH + 2*NG)*HD */

// ---------------- scratch (device globals; allocation-free) ----------------
__device__ float g_h[Tc * Dc];
__device__ float g_x[Tc * Dc];
__device__ float g_qkv[Tc * QKVW];
__device__ float g_q[NHc * Tc * HDc];      // [h][t][d]
__device__ float g_kf[NGc * Sc * HDc];     // [g][s][d]
__device__ float g_vf[NGc * HDc * Sc];     // [g][d][s]
__device__ float g_sc[NHc * Tc * Sc];      // [h][t][s]
__device__ float g_attn[Tc * NHc * HDc];   // [t][h*64+d]
__device__ float g_t1[Tc * Dc];
__device__ float g_gate[Tc * FFc];
__device__ float g_up[Tc * FFc];

// ---------------- tf32 mma helpers ----------------
__device__ __forceinline__ void ldsm4(uint32_t* r, uint32_t addr) {
    asm volatile("ldmatrix.sync.aligned.m8n8.x4.shared.b16 {%0,%1,%2,%3},[%4];\n"
                 : "=r"(r[0]), "=r"(r[1]), "=r"(r[2]), "=r"(r[3])
                 : "r"(addr));
}

__device__ __forceinline__ void split1(uint32_t raw, uint32_t& hi, uint32_t& lo) {
    float x = __uint_as_float(raw);
    uint32_t h;
    asm("cvt.rna.tf32.f32 %0,%1;" : "=r"(h) : "f"(x));
    float l = x - __uint_as_float(h);
    uint32_t lw;
    asm("cvt.rna.tf32.f32 %0,%1;" : "=r"(lw) : "f"(l));
    hi = h; lo = lw;
}

__device__ __forceinline__ void mma_tf32(float* c, const uint32_t* a, const uint32_t* b) {
    asm volatile(
        "mma.sync.aligned.m16n8k8.row.col.f32.tf32.tf32.f32 "
        "{%0,%1,%2,%3},{%4,%5,%6,%7},{%8,%9},{%0,%1,%2,%3};\n"
        : "+f"(c[0]), "+f"(c[1]), "+f"(c[2]), "+f"(c[3])
        : "r"(a[0]), "r"(a[1]), "r"(a[2]), "r"(a[3]), "r"(b[0]), "r"(b[1]));
}

// hi/lo split mma: acc += A*B with fp32-class accuracy (3 tf32 mmas)
__device__ __forceinline__ void mma_split(float* c, const uint32_t* ahi, const uint32_t* alo,
                                          const uint32_t* bhi, const uint32_t* blo) {
    mma_tf32(c, ahi, blo);
    mma_tf32(c, alo, bhi);
    mma_tf32(c, ahi, bhi);
}

// ---------------- reduction helpers ----------------
__device__ __forceinline__ float blockReduceSum(float v) {
    __shared__ float sh[8];
    __syncthreads();
    int lane = threadIdx.x & 31, w = threadIdx.x >> 5;
#pragma unroll
    for (int o = 16; o; o >>= 1) v += __shfl_down_sync(0xffffffffu, v, o);
    if (lane == 0) sh[w] = v;
    __syncthreads();
    int nw = blockDim.x >> 5;
    if (w == 0) {
        v = (lane < nw) ? sh[lane] : 0.f;
#pragma unroll
        for (int o = 4; o; o >>= 1) v += __shfl_down_sync(0xffffffffu, v, o);
        if (lane == 0) sh[0] = v;
    }
    __syncthreads();
    return sh[0];
}

__device__ __forceinline__ float blockReduceMax(float v) {
    __shared__ float sh[8];
    __syncthreads();
    int lane = threadIdx.x & 31, w = threadIdx.x >> 5;
#pragma unroll
    for (int o = 16; o; o >>= 1) v = fmaxf(v, __shfl_down_sync(0xffffffffu, v, o));
    if (lane == 0) sh[w] = v;
    __syncthreads();
    int nw = blockDim.x >> 5;
    if (w == 0) {
        v = (lane < nw) ? sh[lane] : -3.4e38f;
#pragma unroll
        for (int o = 4; o; o >>= 1) v = fmaxf(v, __shfl_down_sync(0xffffffffu, v, o));
        if (lane == 0) sh[0] = v;
    }
    __syncthreads();
    return sh[0];
}

// ---------------- elementwise kernels ----------------
__global__ void k_copy(float* __restrict__ dst, const float* __restrict__ src, int n) {
    int i = blockIdx.x * blockDim.x + threadIdx.x;
    if (i < n) dst[i] = src[i];
}

__global__ void k_rmsnorm(const float* __restrict__ in, const float* __restrict__ w,
                          float* __restrict__ out) {
    int row = blockIdx.x;
    const float* x = in + row * Dc;
    float ss = 0.f;
    for (int d = threadIdx.x; d < Dc; d += blockDim.x) { float v = x[d]; ss += v * v; }
    float tot = blockReduceSum(ss);
    float rs = rsqrtf(tot / (float)Dc + 1e-6f);
    for (int d = threadIdx.x; d < Dc; d += blockDim.x)
        out[row * Dc + d] = x[d] * rs * (1.f + w[d]);
}

__global__ void k_add_rmsnorm(float* __restrict__ h, const float* __restrict__ in,
                              const float* __restrict__ w) {
    int row = blockIdx.x;
    const float* x = in + row * Dc;
    float ss = 0.f;
    for (int d = threadIdx.x; d < Dc; d += blockDim.x) { float v = x[d]; ss += v * v; }
    float tot = blockReduceSum(ss);
    float rs = rsqrtf(tot / (float)Dc + 1e-6f);
    for (int d = threadIdx.x; d < Dc; d += blockDim.x)
        h[row * Dc + d] += x[d] * rs * (1.f + w[d]);
}

__global__ void k_gelumul(float* __restrict__ g, const float* __restrict__ u, int n) {
    int i = blockIdx.x * blockDim.x + threadIdx.x;
    if (i < n) {
        float x = g[i];
        float t = tanhf(0.7978845608028654f * (x + 0.044715f * x * x * x));
        g[i] = 0.5f * x * (1.f + t) * u[i];
    }
}

// ---------------- cache copies ----------------
__global__ void k_copy_kcache(const float* __restrict__ src, float* __restrict__ kf) {
    int i = blockIdx.x * blockDim.x + threadIdx.x;
    if (i >= NGc * CACHEc * HDc) return;
    int g = i / (CACHEc * HDc);
    int r = i - g * (CACHEc * HDc);
    kf[g * Sc * HDc + r] = src[i];
}

__global__ void k_copy_vcache(const float* __restrict__ src, float* __restrict__ vf) {
    int i = blockIdx.x * blockDim.x + threadIdx.x;
    if (i >= NGc * HDc * CACHEc) return;
    int g = i / (HDc * CACHEc);
    int r = i - g * (HDc * CACHEc);
    int d = r / CACHEc;
    int s = r - d * CACHEc;
    vf[(g * HDc + d) * Sc + s] = src[i];
}

// ---------------- qkv split: head rmsnorm + rope + cache append ----------------
__global__ void k_qkprep(const float* __restrict__ qkv,
                         const float* __restrict__ qw, const float* __restrict__ kw,
                         const float* __restrict__ cos_, const float* __restrict__ sin_,
                         float* __restrict__ qout, float* __restrict__ kf,
                         float* __restrict__ vf) {
    int t = blockIdx.x, g = blockIdx.y, d = threadIdx.x;  // 64 threads
    const float* base = qkv + ((t * NGc + g) * (GSc + 2)) * HDc;
    __shared__ float sh[HDc];
    __shared__ float r2[2];
    float c = cos_[t * HDc + d], s = sin_[t * HDc + d];
#pragma unroll
    for (int j = 0; j <= GSc; j++) {
        float v = base[j * HDc + d];
        float sq = v * v;
#pragma unroll
        for (int o = 16; o; o >>= 1) sq += __shfl_down_sync(0xffffffffu, sq, o);
        if ((d & 31) == 0) r2[d >> 5] = sq;
        __syncthreads();
        float tot = r2[0] + r2[1];
        float rs = rsqrtf(tot * (1.f / (float)HDc) + 1e-6f);
        const float* wgt = (j < GSc) ? qw : kw;
        float nv = v * rs * (1.f + wgt[d]);
        sh[d] = nv;
        __syncthreads();
        float rot = (d < 32) ? -sh[d + 32] : sh[d - 32];
        float outv = nv * c + rot * s;
        if (j < GSc) qout[((g * GSc + j) * Tc + t) * HDc + d] = outv;
        else kf[(g * Sc + CACHEc + t) * HDc + d] = outv;
        __syncthreads();
    }
    vf[(g * HDc + d) * Sc + CACHEc + t] = base[(GSc + 2 - 1) * HDc + d];
}

// ============ Tensor-core GEMM: C[M,N] = A[M,K]@B[K,N], row-major ============
// Block 128x64, BK=32, 256 threads (8 warps, 4x2), warp tile 32x32.
// A fragments via ldmatrix from As[row][k]; B fragments via conflict-free LDS
// from Bs[k][n]. Split-tf32 (3 mma) for fp32-class accuracy.
#define MM_BM 128
#define MM_BN 64
#define MM_BK 32
#define MM_PAD 4
__global__ void __launch_bounds__(256) k_mm(const float* __restrict__ A,
                                            const float* __restrict__ B,
                                            float* __restrict__ C,
                                            int M, int N, int K) {
    __shared__ float As[MM_BM][MM_BK + MM_PAD];  // stride 36 floats (144B, 16B mult)
    __shared__ float Bs[MM_BK][MM_BN];
    int tid = threadIdx.x, lane = tid & 31, warp = tid >> 5;
    int wm = warp >> 1, wn = warp & 1;
    int bm = blockIdx.y * MM_BM, bn = blockIdx.x * MM_BN;
    float acc[2][4][4] = {};
    uint32_t as_base = (uint32_t)__cvta_generic_to_shared(&As[0][0]);
    int arow = wm * 32 + (lane & 15);
    int acol = (lane >> 4) * 4;

    for (int k0 = 0; k0 < K; k0 += MM_BK) {
#pragma unroll
        for (int i = 0; i < 4; i++) {
            int id = tid + i * 256;
            int r = id >> 3, c = (id & 7) << 2;
            float4 v = *(const float4*)(A + (size_t)(bm + r) * K + k0 + c);
            *(float4*)&As[r][c] = v;
        }
#pragma unroll
        for (int i = 0; i < 2; i++) {
            int id = tid + i * 256;
            int r = id >> 4, c = (id & 15) << 2;
            float4 v = *(const float4*)(B + (size_t)(k0 + r) * N + bn + c);
            *(float4*)&Bs[r][c] = v;
        }
        __syncthreads();
#pragma unroll
        for (int ks = 0; ks < 4; ks++) {
            uint32_t ahi[2][4], alo[2][4];
#pragma unroll
            for (int mt = 0; mt < 2; mt++) {
                uint32_t a[4];
                uint32_t addr = as_base +
                    (((arow + mt * 16) * (MM_BK + MM_PAD) + ks * 8 + acol) << 2);
                ldsm4(a, addr);
#pragma unroll
                for (int q = 0; q < 4; q++) split1(a[q], ahi[mt][q], alo[mt][q]);
            }
            uint32_t bhi[4][2], blo[4][2];
#pragma unroll
            for (int nt = 0; nt < 4; nt++) {
                int nc = wn * 32 + nt * 8 + (lane >> 2);
                uint32_t b0 = __float_as_uint(Bs[ks * 8 + (lane & 3)][nc]);
                uint32_t b1 = __float_as_uint(Bs[ks * 8 + (lane & 3) + 4][nc]);
                split1(b0, bhi[nt][0], blo[nt][0]);
                split1(b1, bhi[nt][1], blo[nt][1]);
            }
#pragma unroll
            for (int mt = 0; mt < 2; mt++)
#pragma unroll
                for (int nt = 0; nt < 4; nt++)
                    mma_split(acc[mt][nt], ahi[mt], alo[mt], bhi[nt], blo[nt]);
        }
        __syncthreads();
    }
#pragma unroll
    for (int mt = 0; mt < 2; mt++)
#pragma unroll
        for (int nt = 0; nt < 4; nt++) {
            int r0 = bm + wm * 32 + mt * 16 + (lane >> 2);
            int cn = bn + wn * 32 + nt * 8 + 2 * (lane & 3);
            *(float2*)(C + (size_t)r0 * N + cn) =
                make_float2(acc[mt][nt][0], acc[mt][nt][1]);
            *(float2*)(C + (size_t)(r0 + 8) * N + cn) =
                make_float2(acc[mt][nt][2], acc[mt][nt][3]);
        }
}

// ============ scores: QK^T (tensor core) + softcap + analytic mask ============
// Tile 64(t) x 64(s), K=64. 128 threads = 4 warps (2x2), warp 32x32.
// Both A(Q) and B(K) are [row][k] layouts -> ldmatrix for both.
#define SC_PAD 4
__global__ void __launch_bounds__(128) k_scores(const float* __restrict__ q,
                                                const float* __restrict__ kf,
                                                float* __restrict__ sc, int is_local) {
    __shared__ float Qs[64][64 + SC_PAD];  // stride 68 floats = 272B
    __shared__ float Ks[64][64 + SC_PAD];
    int h = blockIdx.z, g = h / GSc;
    int t0 = blockIdx.y * 64, s0 = blockIdx.x * 64;
    int tid = threadIdx.x, lane = tid & 31, warp = tid >> 5;
    int wm = warp >> 1, wn = warp & 1;
    const float* Q = q + (size_t)h * Tc * HDc;
    const float* Kp = kf + (size_t)g * Sc * HDc;
#pragma unroll
    for (int i = 0; i < 8; i++) {
        int id = tid + i * 128;
        int r = id >> 4, c = (id & 15) << 2;
        *(float4*)&Qs[r][c] = *(const float4*)(Q + (size_t)(t0 + r) * HDc + c);
        *(float4*)&Ks[r][c] = *(const float4*)(Kp + (size_t)(s0 + r) * HDc + c);
    }
    __syncthreads();
    uint32_t qs_base = (uint32_t)__cvta_generic_to_shared(&Qs[0][0]);
    uint32_t ks_base = (uint32_t)__cvta_generic_to_shared(&Ks[0][0]);
    int arow = wm * 32 + (lane & 15);
    int acol4 = (lane >> 4) * 4;
    int brow = wn * 32 + (lane & 7) + ((lane >> 4) << 3);  // within 16-row pair
    int bcol4 = (lane & 8) ? 4 : 0;
    float acc[2][4][4] = {};
#pragma unroll
    for (int ks = 0; ks < 8; ks++) {
        uint32_t ahi[2][4], alo[2][4];
#pragma unroll
        for (int mt = 0; mt < 2; mt++) {
            uint32_t a[4];
            uint32_t addr = qs_base + (((arow + mt * 16) * (64 + SC_PAD) + ks * 8 + acol4) << 2);
            ldsm4(a, addr);
#pragma unroll
            for (int qd = 0; qd < 4; qd++) split1(a[qd], ahi[mt][qd], alo[mt][qd]);
        }
        uint32_t bhi[4][2], blo[4][2];
#pragma unroll
        for (int p = 0; p < 2; p++) {  // p covers n-tiles 2p, 2p+1
            uint32_t b[4];
            uint32_t addr = ks_base + (((brow + p * 16) * (64 + SC_PAD) + ks * 8 + bcol4) << 2);
            ldsm4(b, addr);
            split1(b[0], bhi[2 * p][0], blo[2 * p][0]);
            split1(b[1], bhi[2 * p][1], blo[2 * p][1]);
            split1(b[2], bhi[2 * p + 1][0], blo[2 * p + 1][0]);
            split1(b[3], bhi[2 * p + 1][1], blo[2 * p + 1][1]);
        }
#pragma unroll
        for (int mt = 0; mt < 2; mt++)
#pragma unroll
            for (int nt = 0; nt < 4; nt++)
                mma_split(acc[mt][nt], ahi[mt], alo[mt], bhi[nt], blo[nt]);
    }
    const float scale = 0.125f;
#pragma unroll
    for (int mt = 0; mt < 2; mt++)
#pragma unroll
        for (int nt = 0; nt < 4; nt++)
#pragma unroll
            for (int e = 0; e < 4; e++) {
                int t = t0 + wm * 32 + mt * 16 + (lane >> 2) + (e >= 2 ? 8 : 0);
                int sp = s0 + wn * 32 + nt * 8 + 2 * (lane & 3) + (e & 1);
                float v = tanhf(acc[mt][nt][e] * scale * 0.02f) * 50.f;
                int qpos = CACHEc + t;
                bool ok = (sp <= qpos) && (!is_local || sp > qpos - WINc);
                sc[((size_t)h * Tc + t) * Sc + sp] = ok ? v : v - 1e9f;
            }
}

// ---------------- softmax over rows of length S ----------------
__global__ void k_softmax(float* __restrict__ sc) {
    float* r = sc + (size_t)blockIdx.x * Sc;
    float m = -3.4e38f;
    for (int i = threadIdx.x; i < Sc; i += blockDim.x) m = fmaxf(m, r[i]);
    m = blockReduceMax(m);
    float sum = 0.f;
    for (int i = threadIdx.x; i < Sc; i += blockDim.x) {
        float e = __expf(r[i] - m);
        r[i] = e;
        sum += e;
    }
    sum = blockReduceSum(sum);
    float inv = 1.f / sum;
    for (int i = threadIdx.x; i < Sc; i += blockDim.x) r[i] *= inv;
}

// ============ attn = P @ V^T (tensor core) ============
// Tile 64(t) x 64(d), K=2048 chunked by 64. 256 threads = 8 warps (2x4),
// warp tile 32x16. A=P [t][s], B=V [d][s]: both [row][k] -> ldmatrix.
__global__ void __launch_bounds__(256) k_attnv(const float* __restrict__ sc,
                                               const float* __restrict__ vf,
                                               float* __restrict__ attn) {
    __shared__ float Ps[64][64 + SC_PAD];
    __shared__ float Vs[64][64 + SC_PAD];
    int h = blockIdx.y, g = h / GSc;
    int t0 = blockIdx.x * 64;
    int tid = threadIdx.x, lane = tid & 31, warp = tid >> 5;
    int wm = warp >> 2, wn = warp & 3;  // 2 x 4
    const float* P = sc + (size_t)h * Tc * Sc;
    const float* Vv = vf + (size_t)g * HDc * Sc;
    uint32_t ps_base = (uint32_t)__cvta_generic_to_shared(&Ps[0][0]);
    uint32_t vs_base = (uint32_t)__cvta_generic_to_shared(&Vs[0][0]);
    int arow = wm * 32 + (lane & 15);
    int acol4 = (lane >> 4) * 4;
    int brow = wn * 16 + (lane & 7) + ((lane >> 4) << 3);
    int bcol4 = (lane & 8) ? 4 : 0;
    float acc[2][2][4] = {};
    for (int s0 = 0; s0 < Sc; s0 += 64) {
#pragma unroll
        for (int i = 0; i < 4; i++) {
            int id = tid + i * 256;
            int r = id >> 4, c = (id & 15) << 2;
            *(float4*)&Ps[r][c] = *(const float4*)(P + (size_t)(t0 + r) * Sc + s0 + c);
            *(float4*)&Vs[r][c] = *(const float4*)(Vv + (size_t)r * Sc + s0 + c);
        }
        __syncthreads();
#pragma unroll
        for (int ks = 0; ks < 8; ks++) {
            uint32_t ahi[2][4], alo[2][4];
#pragma unroll
            for (int mt = 0; mt < 2; mt++) {
                uint32_t a[4];
                uint32_t addr = ps_base + (((arow + mt * 16) * (64 + SC_PAD) + ks * 8 + acol4) << 2);
                ldsm4(a, addr);
#pragma unroll
                for (int qd = 0; qd < 4; qd++) split1(a[qd], ahi[mt][qd], alo[mt][qd]);
            }
            uint32_t bhi[2][2], blo[2][2];
            {
                uint32_t b[4];
                uint32_t addr = vs_base + ((brow * (64 + SC_PAD) + ks * 8 + bcol4) << 2);
                ldsm4(b, addr);
                split1(b[0], bhi[0][0], blo[0][0]);
                split1(b[1], bhi[0][1], blo[0][1]);
                split1(b[2], bhi[1][0], blo[1][0]);
                split1(b[3], bhi[1][1], blo[1][1]);
            }
#pragma unroll
            for (int mt = 0; mt < 2; mt++)
#pragma unroll
                for (int nt = 0; nt < 2; nt++)
                    mma_split(acc[mt][nt], ahi[mt], alo[mt], bhi[nt], blo[nt]);
        }
        __syncthreads();
    }
#pragma unroll
    for (int mt = 0; mt < 2; mt++)
#pragma unroll
        for (int nt = 0; nt < 2; nt++) {
            int t = t0 + wm * 32 + mt * 16 + (lane >> 2);
            int d = wn * 16 + nt * 8 + 2 * (lane & 3);
            *(float2*)(attn + (size_t)t * (NHc * HDc) + h * HDc + d) =
                make_float2(acc[mt][nt][0], acc[mt][nt][1]);
            *(float2*)(attn + (size_t)(t + 8) * (NHc * HDc) + h * HDc + d) =
                make_float2(acc[mt][nt][2], acc[mt][nt][3]);
        }
}

// ---------------- host ----------------
extern "C" void kernel_launch(void* const* d_in, const int* in_sizes, int n_in,
                              void* d_out, int out_size) {
    const float *embeddings = 0, *kvk = 0, *kvv = 0, *pre_attn = 0, *wqkv = 0,
                *qnorm = 0, *knorm = 0, *wout = 0, *post_attn = 0, *pre_ff = 0,
                *wgate = 0, *wup = 0, *wdown = 0, *post_ff = 0, *finalw = 0,
                *wlm = 0, *cosg = 0, *sing = 0, *cosl = 0, *sinl = 0;
    int kv_n = 0, n19968 = 0, n1664 = 0, n40 = 0, n32k = 0;
    for (int i = 0; i < n_in; i++) {
        const float* p = (const float*)d_in[i];
        int s = in_sizes[i];
        if (s == 393216) embeddings = p;
        else if (s == 10223616) { if (kv_n++ == 0) kvk = p; else kvv = p; }
        else if (s == 19968) {
            if (n19968 == 0) pre_attn = p;
            else if (n19968 == 1) post_attn = p;
            else if (n19968 == 2) pre_ff = p;
            else post_ff = p;
            n19968++;
        }
        else if (s == 25559040) wqkv = p;
        else if (s == 1664) { if (n1664++ == 0) qnorm = p; else knorm = p; }
        else if (s == 15335424) wout = p;
        else if (s == 40894464) {
            if (n40 == 0) wgate = p;
            else if (n40 == 1) wup = p;
            else wdown = p;
            n40++;
        }
        else if (s == 768) finalw = p;
        else if (s == 24576000) wlm = p;
        else if (s == 32768) {
            if (n32k == 0) cosg = p;
            else if (n32k == 1) sing = p;
            else if (n32k == 2) cosl = p;
            else sinl = p;
            n32k++;
        }
    }

    float *ph, *px, *pqkv, *pq, *pkf, *pvf, *psc, *pattn, *pt1, *pgate, *pup;
    cudaGetSymbolAddress((void**)&ph, g_h);
    cudaGetSymbolAddress((void**)&px, g_x);
    cudaGetSymbolAddress((void**)&pqkv, g_qkv);
    cudaGetSymbolAddress((void**)&pq, g_q);
    cudaGetSymbolAddress((void**)&pkf, g_kf);
    cudaGetSymbolAddress((void**)&pvf, g_vf);
    cudaGetSymbolAddress((void**)&psc, g_sc);
    cudaGetSymbolAddress((void**)&pattn, g_attn);
    cudaGetSymbolAddress((void**)&pt1, g_t1);
    cudaGetSymbolAddress((void**)&pgate, g_gate);
    cudaGetSymbolAddress((void**)&pup, g_up);

    k_copy<<<(Tc * Dc + 255) / 256, 256>>>(ph, embeddings, Tc * Dc);

    for (int i = 0; i < Lc; i++) {
        int is_local = ((i + 1) % 6 == 0) ? 1 : 0;
        const float* cs = is_local ? cosl : cosg;
        const float* sn = is_local ? sinl : sing;

        k_copy_kcache<<<(NGc * CACHEc * HDc + 255) / 256, 256>>>(
            kvk + (size_t)i * NGc * CACHEc * HDc, pkf);
        k_copy_vcache<<<(NGc * HDc * CACHEc + 255) / 256, 256>>>(
            kvv + (size_t)i * NGc * HDc * CACHEc, pvf);

        k_rmsnorm<<<Tc, 256>>>(ph, pre_attn + i * Dc, px);
        k_mm<<<dim3(QKVW / MM_BN, Tc / MM_BM), 256>>>(
            px, wqkv + (size_t)i * Dc * QKVW, pqkv, Tc, QKVW, Dc);
        k_qkprep<<<dim3(Tc, NGc), HDc>>>(pqkv, qnorm + i * HDc, knorm + i * HDc,
                                         cs, sn, pq, pkf, pvf);
        k_scores<<<dim3(Sc / 64, Tc / 64, NHc), 128>>>(pq, pkf, psc, is_local);
        k_softmax<<<NHc * Tc, 256>>>(psc);
        k_attnv<<<dim3(Tc / 64, NHc), 256>>>(psc, pvf, pattn);
        k_mm<<<dim3(Dc / MM_BN, Tc / MM_BM), 256>>>(
            pattn, wout + (size_t)i * Dc * Dc, pt1, Tc, Dc, NHc * HDc);
        k_add_rmsnorm<<<Tc, 256>>>(ph, pt1, post_attn + i * Dc);

        k_rmsnorm<<<Tc, 256>>>(ph, pre_ff + i * Dc, px);
        k_mm<<<dim3(FFc / MM_BN, Tc / MM_BM), 256>>>(
            px, wgate + (size_t)i * Dc * FFc, pgate, Tc, FFc, Dc);
        k_mm<<<dim3(FFc / MM_BN, Tc / MM_BM), 256>>>(
            px, wup + (size_t)i * Dc * FFc, pup, Tc, FFc, Dc);
        k_gelumul<<<(Tc * FFc + 255) / 256, 256>>>(pgate, pup, Tc * FFc);
        k_mm<<<dim3(Dc / MM_BN, Tc / MM_BM), 256>>>(
            pgate, wdown + (size_t)i * FFc * Dc, pt1, Tc, Dc, FFc);
        k_add_rmsnorm<<<Tc, 256>>>(ph, pt1, post_ff + i * Dc);
    }

    k_rmsnorm<<<Tc, 256>>>(ph, finalw, px);
    k_mm<<<dim3(Vocab / MM_BN, Tc / MM_BM), 256>>>(px, wlm, (float*)d_out,
                                                   Tc, Vocab, Dc);
}

// round 3
// speedup vs baseline: 1.2094x; 1.0008x over previous
#include <cuda_runtime.h>
#include <math.h>
#include <stdint.h>

#define Lc 26
#define Tc 512
#define Dc 768
#define NHc 12
#define NGc 4
#define GSc 3
#define HDc 64
#define FFc 2048
#define CACHEc 1536
#define Sc 2048
#define Vocab 32000
#define WINc 512
#define QKVW 1280  /* (NH + 2*NG)*HD */

// ---------------- scratch (device globals; allocation-free) ----------------
__device__ float g_h[Tc * Dc];
__device__ float g_x[Tc * Dc];
__device__ float g_qkv[Tc * QKVW];
__device__ float g_q[NHc * Tc * HDc];      // [h][t][d]
__device__ float g_kf[NGc * Sc * HDc];     // [g][s][d]
__device__ float g_vf[NGc * HDc * Sc];     // [g][d][s]
__device__ float g_sc[NHc * Tc * Sc];      // [h][t][s]
__device__ float g_attn[Tc * NHc * HDc];   // [t][h*64+d]
__device__ float g_t1[Tc * Dc];
__device__ float g_gate[Tc * FFc];
__device__ float g_up[Tc * FFc];

// ---------------- tf32 mma helpers ----------------
__device__ __forceinline__ void ldsm4(uint32_t* r, uint32_t addr) {
    asm volatile("ldmatrix.sync.aligned.m8n8.x4.shared.b16 {%0,%1,%2,%3},[%4];\n"
                 : "=r"(r[0]), "=r"(r[1]), "=r"(r[2]), "=r"(r[3])
                 : "r"(addr));
}

__device__ __forceinline__ void split1(uint32_t raw, uint32_t& hi, uint32_t& lo) {
    float x = __uint_as_float(raw);
    uint32_t h;
    asm("cvt.rna.tf32.f32 %0,%1;" : "=r"(h) : "f"(x));
    float l = x - __uint_as_float(h);
    uint32_t lw;
    asm("cvt.rna.tf32.f32 %0,%1;" : "=r"(lw) : "f"(l));
    hi = h; lo = lw;
}

__device__ __forceinline__ void mma_tf32(float* c, const uint32_t* a, const uint32_t* b) {
    asm volatile(
        "mma.sync.aligned.m16n8k8.row.col.f32.tf32.tf32.f32 "
        "{%0,%1,%2,%3},{%4,%5,%6,%7},{%8,%9},{%0,%1,%2,%3};\n"
        : "+f"(c[0]), "+f"(c[1]), "+f"(c[2]), "+f"(c[3])
        : "r"(a[0]), "r"(a[1]), "r"(a[2]), "r"(a[3]), "r"(b[0]), "r"(b[1]));
}

// hi/lo split mma: acc += A*B with fp32-class accuracy (3 tf32 mmas)
__device__ __forceinline__ void mma_split(float* c, const uint32_t* ahi, const uint32_t* alo,
                                          const uint32_t* bhi, const uint32_t* blo) {
    mma_tf32(c, ahi, blo);
    mma_tf32(c, alo, bhi);
    mma_tf32(c, ahi, bhi);
}

// ---------------- reduction helpers ----------------
__device__ __forceinline__ float blockReduceSum(float v) {
    __shared__ float sh[8];
    __syncthreads();
    int lane = threadIdx.x & 31, w = threadIdx.x >> 5;
#pragma unroll
    for (int o = 16; o; o >>= 1) v += __shfl_down_sync(0xffffffffu, v, o);
    if (lane == 0) sh[w] = v;
    __syncthreads();
    int nw = blockDim.x >> 5;
    if (w == 0) {
        v = (lane < nw) ? sh[lane] : 0.f;
#pragma unroll
        for (int o = 4; o; o >>= 1) v += __shfl_down_sync(0xffffffffu, v, o);
        if (lane == 0) sh[0] = v;
    }
    __syncthreads();
    return sh[0];
}

__device__ __forceinline__ float blockReduceMax(float v) {
    __shared__ float sh[8];
    __syncthreads();
    int lane = threadIdx.x & 31, w = threadIdx.x >> 5;
#pragma unroll
    for (int o = 16; o; o >>= 1) v = fmaxf(v, __shfl_down_sync(0xffffffffu, v, o));
    if (lane == 0) sh[w] = v;
    __syncthreads();
    int nw = blockDim.x >> 5;
    if (w == 0) {
        v = (lane < nw) ? sh[lane] : -3.4e38f;
#pragma unroll
        for (int o = 4; o; o >>= 1) v = fmaxf(v, __shfl_down_sync(0xffffffffu, v, o));
        if (lane == 0) sh[0] = v;
    }
    __syncthreads();
    return sh[0];
}

// ---------------- elementwise kernels ----------------
__global__ void k_copy(float* __restrict__ dst, const float* __restrict__ src, int n) {
    int i = blockIdx.x * blockDim.x + threadIdx.x;
    if (i < n) dst[i] = src[i];
}

__global__ void k_rmsnorm(const float* __restrict__ in, const float* __restrict__ w,
                          float* __restrict__ out) {
    int row = blockIdx.x;
    const float* x = in + row * Dc;
    float ss = 0.f;
    for (int d = threadIdx.x; d < Dc; d += blockDim.x) { float v = x[d]; ss += v * v; }
    float tot = blockReduceSum(ss);
    float rs = rsqrtf(tot / (float)Dc + 1e-6f);
    for (int d = threadIdx.x; d < Dc; d += blockDim.x)
        out[row * Dc + d] = x[d] * rs * (1.f + w[d]);
}

__global__ void k_add_rmsnorm(float* __restrict__ h, const float* __restrict__ in,
                              const float* __restrict__ w) {
    int row = blockIdx.x;
    const float* x = in + row * Dc;
    float ss = 0.f;
    for (int d = threadIdx.x; d < Dc; d += blockDim.x) { float v = x[d]; ss += v * v; }
    float tot = blockReduceSum(ss);
    float rs = rsqrtf(tot / (float)Dc + 1e-6f);
    for (int d = threadIdx.x; d < Dc; d += blockDim.x)
        h[row * Dc + d] += x[d] * rs * (1.f + w[d]);
}

__global__ void k_gelumul(float* __restrict__ g, const float* __restrict__ u, int n) {
    int i = blockIdx.x * blockDim.x + threadIdx.x;
    if (i < n) {
        float x = g[i];
        float t = tanhf(0.7978845608028654f * (x + 0.044715f * x * x * x));
        g[i] = 0.5f * x * (1.f + t) * u[i];
    }
}

// ---------------- cache copies ----------------
__global__ void k_copy_kcache(const float* __restrict__ src, float* __restrict__ kf) {
    int i = blockIdx.x * blockDim.x + threadIdx.x;
    if (i >= NGc * CACHEc * HDc) return;
    int g = i / (CACHEc * HDc);
    int r = i - g * (CACHEc * HDc);
    kf[g * Sc * HDc + r] = src[i];
}

__global__ void k_copy_vcache(const float* __restrict__ src, float* __restrict__ vf) {
    int i = blockIdx.x * blockDim.x + threadIdx.x;
    if (i >= NGc * HDc * CACHEc) return;
    int g = i / (HDc * CACHEc);
    int r = i - g * (HDc * CACHEc);
    int d = r / CACHEc;
    int s = r - d * CACHEc;
    vf[(g * HDc + d) * Sc + s] = src[i];
}

// ---------------- qkv split: head rmsnorm + rope + cache append ----------------
__global__ void k_qkprep(const float* __restrict__ qkv,
                         const float* __restrict__ qw, const float* __restrict__ kw,
                         const float* __restrict__ cos_, const float* __restrict__ sin_,
                         float* __restrict__ qout, float* __restrict__ kf,
                         float* __restrict__ vf) {
    int t = blockIdx.x, g = blockIdx.y, d = threadIdx.x;  // 64 threads
    const float* base = qkv + ((t * NGc + g) * (GSc + 2)) * HDc;
    __shared__ float sh[HDc];
    __shared__ float r2[2];
    float c = cos_[t * HDc + d], s = sin_[t * HDc + d];
#pragma unroll
    for (int j = 0; j <= GSc; j++) {
        float v = base[j * HDc + d];
        float sq = v * v;
#pragma unroll
        for (int o = 16; o; o >>= 1) sq += __shfl_down_sync(0xffffffffu, sq, o);
        if ((d & 31) == 0) r2[d >> 5] = sq;
        __syncthreads();
        float tot = r2[0] + r2[1];
        float rs = rsqrtf(tot * (1.f / (float)HDc) + 1e-6f);
        const float* wgt = (j < GSc) ? qw : kw;
        float nv = v * rs * (1.f + wgt[d]);
        sh[d] = nv;
        __syncthreads();
        float rot = (d < 32) ? -sh[d + 32] : sh[d - 32];
        float outv = nv * c + rot * s;
        if (j < GSc) qout[((g * GSc + j) * Tc + t) * HDc + d] = outv;
        else kf[(g * Sc + CACHEc + t) * HDc + d] = outv;
        __syncthreads();
    }
    vf[(g * HDc + d) * Sc + CACHEc + t] = base[(GSc + 2 - 1) * HDc + d];
}

// ============ Tensor-core GEMM: C[M,N] = A[M,K]@B[K,N], row-major ============
// Block 128x64, BK=32, 256 threads (8 warps, 4x2), warp tile 32x32.
// A fragments via ldmatrix from As[row][k]; B fragments via conflict-free LDS
// from Bs[k][n]. Split-tf32 (3 mma) for fp32-class accuracy.
#define MM_BM 128
#define MM_BN 64
#define MM_BK 32
#define MM_PAD 4
__global__ void __launch_bounds__(256) k_mm(const float* __restrict__ A,
                                            const float* __restrict__ B,
                                            float* __restrict__ C,
                                            int M, int N, int K) {
    __shared__ float As[MM_BM][MM_BK + MM_PAD];  // stride 36 floats (144B, 16B mult)
    __shared__ float Bs[MM_BK][MM_BN];
    int tid = threadIdx.x, lane = tid & 31, warp = tid >> 5;
    int wm = warp >> 1, wn = warp & 1;
    int bm = blockIdx.y * MM_BM, bn = blockIdx.x * MM_BN;
    float acc[2][4][4] = {};
    uint32_t as_base = (uint32_t)__cvta_generic_to_shared(&As[0][0]);
    int arow = wm * 32 + (lane & 15);
    int acol = (lane >> 4) * 4;

    for (int k0 = 0; k0 < K; k0 += MM_BK) {
#pragma unroll
        for (int i = 0; i < 4; i++) {
            int id = tid + i * 256;
            int r = id >> 3, c = (id & 7) << 2;
            float4 v = *(const float4*)(A + (size_t)(bm + r) * K + k0 + c);
            *(float4*)&As[r][c] = v;
        }
#pragma unroll
        for (int i = 0; i < 2; i++) {
            int id = tid + i * 256;
            int r = id >> 4, c = (id & 15) << 2;
            float4 v = *(const float4*)(B + (size_t)(k0 + r) * N + bn + c);
            *(float4*)&Bs[r][c] = v;
        }
        __syncthreads();
#pragma unroll
        for (int ks = 0; ks < 4; ks++) {
            uint32_t ahi[2][4], alo[2][4];
#pragma unroll
            for (int mt = 0; mt < 2; mt++) {
                uint32_t a[4];
                uint32_t addr = as_base +
                    (((arow + mt * 16) * (MM_BK + MM_PAD) + ks * 8 + acol) << 2);
                ldsm4(a, addr);
#pragma unroll
                for (int q = 0; q < 4; q++) split1(a[q], ahi[mt][q], alo[mt][q]);
            }
            uint32_t bhi[4][2], blo[4][2];
#pragma unroll
            for (int nt = 0; nt < 4; nt++) {
                int nc = wn * 32 + nt * 8 + (lane >> 2);
                uint32_t b0 = __float_as_uint(Bs[ks * 8 + (lane & 3)][nc]);
                uint32_t b1 = __float_as_uint(Bs[ks * 8 + (lane & 3) + 4][nc]);
                split1(b0, bhi[nt][0], blo[nt][0]);
                split1(b1, bhi[nt][1], blo[nt][1]);
            }
#pragma unroll
            for (int mt = 0; mt < 2; mt++)
#pragma unroll
                for (int nt = 0; nt < 4; nt++)
                    mma_split(acc[mt][nt], ahi[mt], alo[mt], bhi[nt], blo[nt]);
        }
        __syncthreads();
    }
#pragma unroll
    for (int mt = 0; mt < 2; mt++)
#pragma unroll
        for (int nt = 0; nt < 4; nt++) {
            int r0 = bm + wm * 32 + mt * 16 + (lane >> 2);
            int cn = bn + wn * 32 + nt * 8 + 2 * (lane & 3);
            *(float2*)(C + (size_t)r0 * N + cn) =
                make_float2(acc[mt][nt][0], acc[mt][nt][1]);
            *(float2*)(C + (size_t)(r0 + 8) * N + cn) =
                make_float2(acc[mt][nt][2], acc[mt][nt][3]);
        }
}

// ============ scores: QK^T (tensor core) + softcap + analytic mask ============
// Tile 64(t) x 64(s), K=64. 128 threads = 4 warps (2x2), warp 32x32.
// Both A(Q) and B(K) are [row][k] layouts -> ldmatrix for both.
#define SC_PAD 4
__global__ void __launch_bounds__(128) k_scores(const float* __restrict__ q,
                                                const float* __restrict__ kf,
                                                float* __restrict__ sc, int is_local) {
    __shared__ float Qs[64][64 + SC_PAD];  // stride 68 floats = 272B
    __shared__ float Ks[64][64 + SC_PAD];
    int h = blockIdx.z, g = h / GSc;
    int t0 = blockIdx.y * 64, s0 = blockIdx.x * 64;
    int tid = threadIdx.x, lane = tid & 31, warp = tid >> 5;
    int wm = warp >> 1, wn = warp & 1;
    const float* Q = q + (size_t)h * Tc * HDc;
    const float* Kp = kf + (size_t)g * Sc * HDc;
#pragma unroll
    for (int i = 0; i < 8; i++) {
        int id = tid + i * 128;
        int r = id >> 4, c = (id & 15) << 2;
        *(float4*)&Qs[r][c] = *(const float4*)(Q + (size_t)(t0 + r) * HDc + c);
        *(float4*)&Ks[r][c] = *(const float4*)(Kp + (size_t)(s0 + r) * HDc + c);
    }
    __syncthreads();
    uint32_t qs_base = (uint32_t)__cvta_generic_to_shared(&Qs[0][0]);
    uint32_t ks_base = (uint32_t)__cvta_generic_to_shared(&Ks[0][0]);
    int arow = wm * 32 + (lane & 15);
    int acol4 = (lane >> 4) * 4;
    int brow = wn * 32 + (lane & 7) + ((lane >> 4) << 3);  // within 16-row pair
    int bcol4 = (lane & 8) ? 4 : 0;
    float acc[2][4][4] = {};
#pragma unroll
    for (int ks = 0; ks < 8; ks++) {
        uint32_t ahi[2][4], alo[2][4];
#pragma unroll
        for (int mt = 0; mt < 2; mt++) {
            uint32_t a[4];
            uint32_t addr = qs_base + (((arow + mt * 16) * (64 + SC_PAD) + ks * 8 + acol4) << 2);
            ldsm4(a, addr);
#pragma unroll
            for (int qd = 0; qd < 4; qd++) split1(a[qd], ahi[mt][qd], alo[mt][qd]);
        }
        uint32_t bhi[4][2], blo[4][2];
#pragma unroll
        for (int p = 0; p < 2; p++) {  // p covers n-tiles 2p, 2p+1
            uint32_t b[4];
            uint32_t addr = ks_base + (((brow + p * 16) * (64 + SC_PAD) + ks * 8 + bcol4) << 2);
            ldsm4(b, addr);
            split1(b[0], bhi[2 * p][0], blo[2 * p][0]);
            split1(b[1], bhi[2 * p][1], blo[2 * p][1]);
            split1(b[2], bhi[2 * p + 1][0], blo[2 * p + 1][0]);
            split1(b[3], bhi[2 * p + 1][1], blo[2 * p + 1][1]);
        }
#pragma unroll
        for (int mt = 0; mt < 2; mt++)
#pragma unroll
            for (int nt = 0; nt < 4; nt++)
                mma_split(acc[mt][nt], ahi[mt], alo[mt], bhi[nt], blo[nt]);
    }
    const float scale = 0.125f;
#pragma unroll
    for (int mt = 0; mt < 2; mt++)
#pragma unroll
        for (int nt = 0; nt < 4; nt++)
#pragma unroll
            for (int e = 0; e < 4; e++) {
                int t = t0 + wm * 32 + mt * 16 + (lane >> 2) + (e >= 2 ? 8 : 0);
                int sp = s0 + wn * 32 + nt * 8 + 2 * (lane & 3) + (e & 1);
                float v = tanhf(acc[mt][nt][e] * scale * 0.02f) * 50.f;
                int qpos = CACHEc + t;
                bool ok = (sp <= qpos) && (!is_local || sp > qpos - WINc);
                sc[((size_t)h * Tc + t) * Sc + sp] = ok ? v : v - 1e9f;
            }
}

// ---------------- softmax over rows of length S ----------------
__global__ void k_softmax(float* __restrict__ sc) {
    float* r = sc + (size_t)blockIdx.x * Sc;
    float m = -3.4e38f;
    for (int i = threadIdx.x; i < Sc; i += blockDim.x) m = fmaxf(m, r[i]);
    m = blockReduceMax(m);
    float sum = 0.f;
    for (int i = threadIdx.x; i < Sc; i += blockDim.x) {
        float e = __expf(r[i] - m);
        r[i] = e;
        sum += e;
    }
    sum = blockReduceSum(sum);
    float inv = 1.f / sum;
    for (int i = threadIdx.x; i < Sc; i += blockDim.x) r[i] *= inv;
}

// ============ attn = P @ V^T (tensor core) ============
// Tile 64(t) x 64(d), K=2048 chunked by 64. 256 threads = 8 warps (2x4),
// warp tile 32x16. A=P [t][s], B=V [d][s]: both [row][k] -> ldmatrix.
__global__ void __launch_bounds__(256) k_attnv(const float* __restrict__ sc,
                                               const float* __restrict__ vf,
                                               float* __restrict__ attn) {
    __shared__ float Ps[64][64 + SC_PAD];
    __shared__ float Vs[64][64 + SC_PAD];
    int h = blockIdx.y, g = h / GSc;
    int t0 = blockIdx.x * 64;
    int tid = threadIdx.x, lane = tid & 31, warp = tid >> 5;
    int wm = warp >> 2, wn = warp & 3;  // 2 x 4
    const float* P = sc + (size_t)h * Tc * Sc;
    const float* Vv = vf + (size_t)g * HDc * Sc;
    uint32_t ps_base = (uint32_t)__cvta_generic_to_shared(&Ps[0][0]);
    uint32_t vs_base = (uint32_t)__cvta_generic_to_shared(&Vs[0][0]);
    int arow = wm * 32 + (lane & 15);
    int acol4 = (lane >> 4) * 4;
    int brow = wn * 16 + (lane & 7) + ((lane >> 4) << 3);
    int bcol4 = (lane & 8) ? 4 : 0;
    float acc[2][2][4] = {};
    for (int s0 = 0; s0 < Sc; s0 += 64) {
#pragma unroll
        for (int i = 0; i < 4; i++) {
            int id = tid + i * 256;
            int r = id >> 4, c = (id & 15) << 2;
            *(float4*)&Ps[r][c] = *(const float4*)(P + (size_t)(t0 + r) * Sc + s0 + c);
            *(float4*)&Vs[r][c] = *(const float4*)(Vv + (size_t)r * Sc + s0 + c);
        }
        __syncthreads();
#pragma unroll
        for (int ks = 0; ks < 8; ks++) {
            uint32_t ahi[2][4], alo[2][4];
#pragma unroll
            for (int mt = 0; mt < 2; mt++) {
                uint32_t a[4];
                uint32_t addr = ps_base + (((arow + mt * 16) * (64 + SC_PAD) + ks * 8 + acol4) << 2);
                ldsm4(a, addr);
#pragma unroll
                for (int qd = 0; qd < 4; qd++) split1(a[qd], ahi[mt][qd], alo[mt][qd]);
            }
            uint32_t bhi[2][2], blo[2][2];
            {
                uint32_t b[4];
                uint32_t addr = vs_base + ((brow * (64 + SC_PAD) + ks * 8 + bcol4) << 2);
                ldsm4(b, addr);
                split1(b[0], bhi[0][0], blo[0][0]);
                split1(b[1], bhi[0][1], blo[0][1]);
                split1(b[2], bhi[1][0], blo[1][0]);
                split1(b[3], bhi[1][1], blo[1][1]);
            }
#pragma unroll
            for (int mt = 0; mt < 2; mt++)
#pragma unroll
                for (int nt = 0; nt < 2; nt++)
                    mma_split(acc[mt][nt], ahi[mt], alo[mt], bhi[nt], blo[nt]);
        }
        __syncthreads();
    }
#pragma unroll
    for (int mt = 0; mt < 2; mt++)
#pragma unroll
        for (int nt = 0; nt < 2; nt++) {
            int t = t0 + wm * 32 + mt * 16 + (lane >> 2);
            int d = wn * 16 + nt * 8 + 2 * (lane & 3);
            *(float2*)(attn + (size_t)t * (NHc * HDc) + h * HDc + d) =
                make_float2(acc[mt][nt][0], acc[mt][nt][1]);
            *(float2*)(attn + (size_t)(t + 8) * (NHc * HDc) + h * HDc + d) =
                make_float2(acc[mt][nt][2], acc[mt][nt][3]);
        }
}

// ---------------- host ----------------
extern "C" void kernel_launch(void* const* d_in, const int* in_sizes, int n_in,
                              void* d_out, int out_size) {
    const float *embeddings = 0, *kvk = 0, *kvv = 0, *pre_attn = 0, *wqkv = 0,
                *qnorm = 0, *knorm = 0, *wout = 0, *post_attn = 0, *pre_ff = 0,
                *wgate = 0, *wup = 0, *wdown = 0, *post_ff = 0, *finalw = 0,
                *wlm = 0, *cosg = 0, *sing = 0, *cosl = 0, *sinl = 0;
    int kv_n = 0, n19968 = 0, n1664 = 0, n40 = 0, n32k = 0;
    for (int i = 0; i < n_in; i++) {
        const float* p = (const float*)d_in[i];
        int s = in_sizes[i];
        if (s == 393216) embeddings = p;
        else if (s == 10223616) { if (kv_n++ == 0) kvk = p; else kvv = p; }
        else if (s == 19968) {
            if (n19968 == 0) pre_attn = p;
            else if (n19968 == 1) post_attn = p;
            else if (n19968 == 2) pre_ff = p;
            else post_ff = p;
            n19968++;
        }
        else if (s == 25559040) wqkv = p;
        else if (s == 1664) { if (n1664++ == 0) qnorm = p; else knorm = p; }
        else if (s == 15335424) wout = p;
        else if (s == 40894464) {
            if (n40 == 0) wgate = p;
            else if (n40 == 1) wup = p;
            else wdown = p;
            n40++;
        }
        else if (s == 768) finalw = p;
        else if (s == 24576000) wlm = p;
        else if (s == 32768) {
            if (n32k == 0) cosg = p;
            else if (n32k == 1) sing = p;
            else if (n32k == 2) cosl = p;
            else sinl = p;
            n32k++;
        }
    }

    float *ph, *px, *pqkv, *pq, *pkf, *pvf, *psc, *pattn, *pt1, *pgate, *pup;
    cudaGetSymbolAddress((void**)&ph, g_h);
    cudaGetSymbolAddress((void**)&px, g_x);
    cudaGetSymbolAddress((void**)&pqkv, g_qkv);
    cudaGetSymbolAddress((void**)&pq, g_q);
    cudaGetSymbolAddress((void**)&pkf, g_kf);
    cudaGetSymbolAddress((void**)&pvf, g_vf);
    cudaGetSymbolAddress((void**)&psc, g_sc);
    cudaGetSymbolAddress((void**)&pattn, g_attn);
    cudaGetSymbolAddress((void**)&pt1, g_t1);
    cudaGetSymbolAddress((void**)&pgate, g_gate);
    cudaGetSymbolAddress((void**)&pup, g_up);

    k_copy<<<(Tc * Dc + 255) / 256, 256>>>(ph, embeddings, Tc * Dc);

    for (int i = 0; i < Lc; i++) {
        int is_local = ((i + 1) % 6 == 0) ? 1 : 0;
        const float* cs = is_local ? cosl : cosg;
        const float* sn = is_local ? sinl : sing;

        k_copy_kcache<<<(NGc * CACHEc * HDc + 255) / 256, 256>>>(
            kvk + (size_t)i * NGc * CACHEc * HDc, pkf);
        k_copy_vcache<<<(NGc * HDc * CACHEc + 255) / 256, 256>>>(
            kvv + (size_t)i * NGc * HDc * CACHEc, pvf);

        k_rmsnorm<<<Tc, 256>>>(ph, pre_attn + i * Dc, px);
        k_mm<<<dim3(QKVW / MM_BN, Tc / MM_BM), 256>>>(
            px, wqkv + (size_t)i * Dc * QKVW, pqkv, Tc, QKVW, Dc);
        k_qkprep<<<dim3(Tc, NGc), HDc>>>(pqkv, qnorm + i * HDc, knorm + i * HDc,
                                         cs, sn, pq, pkf, pvf);
        k_scores<<<dim3(Sc / 64, Tc / 64, NHc), 128>>>(pq, pkf, psc, is_local);
        k_softmax<<<NHc * Tc, 256>>>(psc);
        k_attnv<<<dim3(Tc / 64, NHc), 256>>>(psc, pvf, pattn);
        k_mm<<<dim3(Dc / MM_BN, Tc / MM_BM), 256>>>(
            pattn, wout + (size_t)i * Dc * Dc, pt1, Tc, Dc, NHc * HDc);
        k_add_rmsnorm<<<Tc, 256>>>(ph, pt1, post_attn + i * Dc);

        k_rmsnorm<<<Tc, 256>>>(ph, pre_ff + i * Dc, px);
        k_mm<<<dim3(FFc / MM_BN, Tc / MM_BM), 256>>>(
            px, wgate + (size_t)i * Dc * FFc, pgate, Tc, FFc, Dc);
        k_mm<<<dim3(FFc / MM_BN, Tc / MM_BM), 256>>>(
            px, wup + (size_t)i * Dc * FFc, pup, Tc, FFc, Dc);
        k_gelumul<<<(Tc * FFc + 255) / 256, 256>>>(pgate, pup, Tc * FFc);
        k_mm<<<dim3(Dc / MM_BN, Tc / MM_BM), 256>>>(
            pgate, wdown + (size_t)i * FFc * Dc, pt1, Tc, Dc, FFc);
        k_add_rmsnorm<<<Tc, 256>>>(ph, pt1, post_ff + i * Dc);
    }

    k_rmsnorm<<<Tc, 256>>>(ph, finalw, px);
    k_mm<<<dim3(Vocab / MM_BN, Tc / MM_BM), 256>>>(px, wlm, (float*)d_out,
                                                   Tc, Vocab, Dc);
}

// round 5
// speedup vs baseline: 2.4907x; 2.0595x over previous
#include <cuda_runtime.h>
#include <cuda_bf16.h>
#include <math.h>
#include <stdint.h>

#define Lc 26
#define Tc 512
#define Dc 768
#define NHc 12
#define NGc 4
#define GSc 3
#define HDc 64
#define FFc 2048
#define CACHEc 1536
#define Sc 2048
#define Vocab 32000
#define WINc 512
#define QKVW 1280
typedef __nv_bfloat16 bf16;

#define SZ_WQKV 25559040
#define SZ_WOUT 15335424
#define SZ_WFF  40894464
#define SZ_WLM  24576000

// ---------------- scratch ----------------
__device__ float g_h[Tc * Dc];
__device__ float g_qkv[Tc * QKVW];
__device__ float g_t1[Tc * Dc];
__device__ bf16 bx_h[Tc * Dc], bx_l[Tc * Dc];
__device__ bf16 bat_h[Tc * Dc], bat_l[Tc * Dc];
__device__ bf16 bgt_h[Tc * FFc], bgt_l[Tc * FFc];
__device__ bf16 bq_h[NHc * Tc * HDc], bq_l[NHc * Tc * HDc];
__device__ bf16 bk_h[NGc * Sc * HDc], bk_l[NGc * Sc * HDc];
__device__ bf16 bv_h[NGc * HDc * Sc], bv_l[NGc * HDc * Sc];
__device__ bf16 wqkv_h[SZ_WQKV], wqkv_l[SZ_WQKV];
__device__ bf16 wout_h[SZ_WOUT], wout_l[SZ_WOUT];
__device__ bf16 wgt_h[SZ_WFF], wgt_l[SZ_WFF];
__device__ bf16 wup_h[SZ_WFF], wup_l[SZ_WFF];
__device__ bf16 wdn_h[SZ_WFF], wdn_l[SZ_WFF];
__device__ bf16 wlm_h[SZ_WLM], wlm_l[SZ_WLM];

// ---------------- asm helpers ----------------
__device__ __forceinline__ uint32_t cvta(const void* p) {
    return (uint32_t)__cvta_generic_to_shared(p);
}
#define LDSM4(r, a) asm volatile( \
    "ldmatrix.sync.aligned.m8n8.x4.shared.b16 {%0,%1,%2,%3},[%4];\n" \
    : "=r"((r)[0]), "=r"((r)[1]), "=r"((r)[2]), "=r"((r)[3]) : "r"(a))
#define LDSM4T(r, a) asm volatile( \
    "ldmatrix.sync.aligned.m8n8.x4.trans.shared.b16 {%0,%1,%2,%3},[%4];\n" \
    : "=r"((r)[0]), "=r"((r)[1]), "=r"((r)[2]), "=r"((r)[3]) : "r"(a))
#define MMA16(c, a, b0, b1) asm volatile( \
    "mma.sync.aligned.m16n8k16.row.col.f32.bf16.bf16.f32 " \
    "{%0,%1,%2,%3},{%4,%5,%6,%7},{%8,%9},{%0,%1,%2,%3};\n" \
    : "+f"((c)[0]), "+f"((c)[1]), "+f"((c)[2]), "+f"((c)[3]) \
    : "r"((a)[0]), "r"((a)[1]), "r"((a)[2]), "r"((a)[3]), "r"(b0), "r"(b1))
#define CPA16(d, s) asm volatile("cp.async.cg.shared.global [%0],[%1],16;\n" :: "r"(d), "l"(s))
#define CPCOMMIT() asm volatile("cp.async.commit_group;\n")
#define CPWAIT(n) asm volatile("cp.async.wait_group %0;\n" :: "n"(n))

__device__ __forceinline__ void splitstore(bf16* ph, bf16* pl, size_t i, float v) {
    bf16 h = __float2bfloat16(v);
    ph[i] = h;
    pl[i] = __float2bfloat16(v - __bfloat162float(h));
}

__device__ __forceinline__ float blockReduceSum(float v) {
    __shared__ float sh[8];
    __syncthreads();
    int lane = threadIdx.x & 31, w = threadIdx.x >> 5;
#pragma unroll
    for (int o = 16; o; o >>= 1) v += __shfl_down_sync(0xffffffffu, v, o);
    if (lane == 0) sh[w] = v;
    __syncthreads();
    int nw = blockDim.x >> 5;
    if (w == 0) {
        v = (lane < nw) ? sh[lane] : 0.f;
#pragma unroll
        for (int o = 4; o; o >>= 1) v += __shfl_down_sync(0xffffffffu, v, o);
        if (lane == 0) sh[0] = v;
    }
    __syncthreads();
    return sh[0];
}

// ---------------- elementwise ----------------
__global__ void k_split4(const float* __restrict__ s, bf16* __restrict__ hi,
                         bf16* __restrict__ lo, int n4) {
    int i = blockIdx.x * blockDim.x + threadIdx.x;
    if (i >= n4) return;
    float4 v = ((const float4*)s)[i];
    size_t b = (size_t)i * 4;
    splitstore(hi, lo, b, v.x);
    splitstore(hi, lo, b + 1, v.y);
    splitstore(hi, lo, b + 2, v.z);
    splitstore(hi, lo, b + 3, v.w);
}

__global__ void k_init(const float* __restrict__ e, const float* __restrict__ w,
                       float* __restrict__ h, bf16* __restrict__ oh, bf16* __restrict__ ol) {
    int row = blockIdx.x;
    const float* x = e + row * Dc;
    float ss = 0.f;
    for (int d = threadIdx.x; d < Dc; d += blockDim.x) { float v = x[d]; ss += v * v; }
    float rs = rsqrtf(blockReduceSum(ss) / Dc + 1e-6f);
    for (int d = threadIdx.x; d < Dc; d += blockDim.x) {
        float v = x[d];
        h[row * Dc + d] = v;
        splitstore(oh, ol, (size_t)row * Dc + d, v * rs * (1.f + w[d]));
    }
}

// h += rmsnorm(t1,wpost); out = split(rmsnorm(h,wpre))
__global__ void k_fuse(float* __restrict__ h, const float* __restrict__ t1,
                       const float* __restrict__ wpost, const float* __restrict__ wpre,
                       bf16* __restrict__ oh, bf16* __restrict__ ol) {
    int row = blockIdx.x;
    const float* x = t1 + row * Dc;
    float ss = 0.f;
    for (int d = threadIdx.x; d < Dc; d += blockDim.x) { float v = x[d]; ss += v * v; }
    float rs = rsqrtf(blockReduceSum(ss) / Dc + 1e-6f);
    float ss2 = 0.f;
    for (int d = threadIdx.x; d < Dc; d += blockDim.x) {
        float hv = h[row * Dc + d] + x[d] * rs * (1.f + wpost[d]);
        h[row * Dc + d] = hv;
        ss2 += hv * hv;
    }
    float rs2 = rsqrtf(blockReduceSum(ss2) / Dc + 1e-6f);
    for (int d = threadIdx.x; d < Dc; d += blockDim.x)
        splitstore(oh, ol, (size_t)row * Dc + d, h[row * Dc + d] * rs2 * (1.f + wpre[d]));
}

__global__ void k_convkv(const float* __restrict__ ks, const float* __restrict__ vs,
                         bf16* __restrict__ kh, bf16* __restrict__ kl,
                         bf16* __restrict__ vh, bf16* __restrict__ vl) {
    int idx = blockIdx.x * blockDim.x + threadIdx.x;
    if (idx < 98304) {
        int i4 = idx * 4;
        int g = i4 / (CACHEc * HDc), r = i4 - g * (CACHEc * HDc);
        size_t dst = (size_t)g * Sc * HDc + r;
        float4 v = ((const float4*)ks)[idx];
        splitstore(kh, kl, dst, v.x); splitstore(kh, kl, dst + 1, v.y);
        splitstore(kh, kl, dst + 2, v.z); splitstore(kh, kl, dst + 3, v.w);
    } else if (idx < 196608) {
        int j4 = (idx - 98304) * 4;
        int row = j4 / CACHEc, c = j4 - row * CACHEc;
        size_t dst = (size_t)row * Sc + c;
        float4 v = ((const float4*)vs)[idx - 98304];
        splitstore(vh, vl, dst, v.x); splitstore(vh, vl, dst + 1, v.y);
        splitstore(vh, vl, dst + 2, v.z); splitstore(vh, vl, dst + 3, v.w);
    }
}

__global__ void k_qkprep(const float* __restrict__ qkv,
                         const float* __restrict__ qw, const float* __restrict__ kw,
                         const float* __restrict__ cos_, const float* __restrict__ sin_) {
    int t = blockIdx.x, g = blockIdx.y, d = threadIdx.x;
    const float* base = qkv + ((t * NGc + g) * (GSc + 2)) * HDc;
    __shared__ float sh[HDc];
    __shared__ float r2[2];
    float c = cos_[t * HDc + d], s = sin_[t * HDc + d];
#pragma unroll
    for (int j = 0; j <= GSc; j++) {
        float v = base[j * HDc + d];
        float sq = v * v;
#pragma unroll
        for (int o = 16; o; o >>= 1) sq += __shfl_down_sync(0xffffffffu, sq, o);
        if ((d & 31) == 0) r2[d >> 5] = sq;
        __syncthreads();
        float rs = rsqrtf((r2[0] + r2[1]) * (1.f / HDc) + 1e-6f);
        const float* wgt = (j < GSc) ? qw : kw;
        float nv = v * rs * (1.f + wgt[d]);
        sh[d] = nv;
        __syncthreads();
        float rot = (d < 32) ? -sh[d + 32] : sh[d - 32];
        float outv = nv * c + rot * s;
        if (j < GSc) splitstore(bq_h, bq_l, ((size_t)(g * GSc + j) * Tc + t) * HDc + d, outv);
        else splitstore(bk_h, bk_l, ((size_t)g * Sc + CACHEc + t) * HDc + d, outv);
        __syncthreads();
    }
    splitstore(bv_h, bv_l, (size_t)(g * HDc + d) * Sc + CACHEc + t, base[(GSc + 1) * HDc + d]);
}

// ============ GEMM 64x64 tile, BK=32, 256 thr, 8 warps (2m x 4n) ============
__global__ void __launch_bounds__(256) k_mm(const bf16* __restrict__ Ah,
                                            const bf16* __restrict__ Al,
                                            const bf16* __restrict__ Bh,
                                            const bf16* __restrict__ Bl,
                                            float* __restrict__ C, int N, int K) {
    __shared__ bf16 sA[2][2][64][40];
    __shared__ bf16 sB[2][2][32][72];
    int tid = threadIdx.x, lane = tid & 31, warp = tid >> 5;
    int wm = warp & 1, wn = warp >> 1;
    int bm = blockIdx.y * 64, bn = blockIdx.x * 64;
    int nIt = K >> 5;
    int ar = tid >> 2, ac = (tid & 3) << 3;
    int br = tid >> 3, bc = (tid & 7) << 3;
    const bf16* pAh = Ah + (size_t)(bm + ar) * K + ac;
    const bf16* pAl = Al + (size_t)(bm + ar) * K + ac;
    const bf16* pBh = Bh + (size_t)br * N + bn + bc;
    const bf16* pBl = Bl + (size_t)br * N + bn + bc;
    float acc[2][2][4] = {};
    CPA16(cvta(&sA[0][0][ar][ac]), pAh); CPA16(cvta(&sA[0][1][ar][ac]), pAl);
    CPA16(cvta(&sB[0][0][br][bc]), pBh); CPA16(cvta(&sB[0][1][br][bc]), pBl);
    CPCOMMIT();
    for (int it = 0; it < nIt; it++) {
        int st = it & 1;
        if (it + 1 < nIt) {
            int k0 = (it + 1) << 5;
            CPA16(cvta(&sA[st ^ 1][0][ar][ac]), pAh + k0);
            CPA16(cvta(&sA[st ^ 1][1][ar][ac]), pAl + k0);
            CPA16(cvta(&sB[st ^ 1][0][br][bc]), pBh + (size_t)k0 * N);
            CPA16(cvta(&sB[st ^ 1][1][br][bc]), pBl + (size_t)k0 * N);
            CPCOMMIT(); CPWAIT(1);
        } else CPWAIT(0);
        __syncthreads();
#pragma unroll
        for (int kp = 0; kp < 2; kp++) {
            uint32_t ah2[2][4], al2[2][4], bh2[4], bl2[4];
#pragma unroll
            for (int mt = 0; mt < 2; mt++) {
                int r = wm * 32 + mt * 16 + (lane & 15), c = kp * 16 + ((lane >> 4) << 3);
                LDSM4(ah2[mt], cvta(&sA[st][0][r][c]));
                LDSM4(al2[mt], cvta(&sA[st][1][r][c]));
            }
            int bg = lane >> 3;
            int kr = kp * 16 + ((bg & 1) << 3) + (lane & 7);
            int nc = wn * 16 + ((bg >> 1) << 3);
            LDSM4T(bh2, cvta(&sB[st][0][kr][nc]));
            LDSM4T(bl2, cvta(&sB[st][1][kr][nc]));
#pragma unroll
            for (int mt = 0; mt < 2; mt++)
#pragma unroll
                for (int nt = 0; nt < 2; nt++) {
                    MMA16(acc[mt][nt], ah2[mt], bh2[2 * nt], bh2[2 * nt + 1]);
                    MMA16(acc[mt][nt], ah2[mt], bl2[2 * nt], bl2[2 * nt + 1]);
                    MMA16(acc[mt][nt], al2[mt], bh2[2 * nt], bh2[2 * nt + 1]);
                }
        }
        __syncthreads();
    }
#pragma unroll
    for (int mt = 0; mt < 2; mt++)
#pragma unroll
        for (int nt = 0; nt < 2; nt++) {
            int r0 = bm + wm * 32 + mt * 16 + (lane >> 2);
            int c0 = bn + wn * 16 + nt * 8 + 2 * (lane & 3);
            *(float2*)(C + (size_t)r0 * N + c0) = make_float2(acc[mt][nt][0], acc[mt][nt][1]);
            *(float2*)(C + (size_t)(r0 + 8) * N + c0) = make_float2(acc[mt][nt][2], acc[mt][nt][3]);
        }
}

// ============ dual GEMM (gate|up) + gelu*mul -> bf16 split ============
__global__ void __launch_bounds__(256) k_mmff(const bf16* __restrict__ Ah,
                                              const bf16* __restrict__ Al,
                                              const bf16* __restrict__ B0h,
                                              const bf16* __restrict__ B0l,
                                              const bf16* __restrict__ B1h,
                                              const bf16* __restrict__ B1l,
                                              bf16* __restrict__ Oh, bf16* __restrict__ Ol) {
    extern __shared__ char dsm[];
    bf16(*sA)[2][64][40] = (bf16(*)[2][64][40])dsm;                    // 20480B
    bf16(*sB0)[2][32][72] = (bf16(*)[2][32][72])(dsm + 20480);         // 18432B
    bf16(*sB1)[2][32][72] = (bf16(*)[2][32][72])(dsm + 20480 + 18432); // 18432B
    const int N = FFc, K = Dc;
    int tid = threadIdx.x, lane = tid & 31, warp = tid >> 5;
    int wm = warp & 1, wn = warp >> 1;
    int bm = blockIdx.y * 64, bn = blockIdx.x * 64;
    int ar = tid >> 2, ac = (tid & 3) << 3;
    int br = tid >> 3, bc = (tid & 7) << 3;
    const bf16* pAh = Ah + (size_t)(bm + ar) * K + ac;
    const bf16* pAl = Al + (size_t)(bm + ar) * K + ac;
    size_t boff = (size_t)br * N + bn + bc;
    float ag[2][2][4] = {}, au[2][2][4] = {};
    CPA16(cvta(&sA[0][0][ar][ac]), pAh); CPA16(cvta(&sA[0][1][ar][ac]), pAl);
    CPA16(cvta(&sB0[0][0][br][bc]), B0h + boff); CPA16(cvta(&sB0[0][1][br][bc]), B0l + boff);
    CPA16(cvta(&sB1[0][0][br][bc]), B1h + boff); CPA16(cvta(&sB1[0][1][br][bc]), B1l + boff);
    CPCOMMIT();
    for (int it = 0; it < (K >> 5); it++) {
        int st = it & 1;
        if (it + 1 < (K >> 5)) {
            int k0 = (it + 1) << 5;
            CPA16(cvta(&sA[st ^ 1][0][ar][ac]), pAh + k0);
            CPA16(cvta(&sA[st ^ 1][1][ar][ac]), pAl + k0);
            CPA16(cvta(&sB0[st ^ 1][0][br][bc]), B0h + boff + (size_t)k0 * N);
            CPA16(cvta(&sB0[st ^ 1][1][br][bc]), B0l + boff + (size_t)k0 * N);
            CPA16(cvta(&sB1[st ^ 1][0][br][bc]), B1h + boff + (size_t)k0 * N);
            CPA16(cvta(&sB1[st ^ 1][1][br][bc]), B1l + boff + (size_t)k0 * N);
            CPCOMMIT(); CPWAIT(1);
        } else CPWAIT(0);
        __syncthreads();
#pragma unroll
        for (int kp = 0; kp < 2; kp++) {
            uint32_t ah2[2][4], al2[2][4], b0h[4], b0l[4], b1h[4], b1l[4];
#pragma unroll
            for (int mt = 0; mt < 2; mt++) {
                int r = wm * 32 + mt * 16 + (lane & 15), c = kp * 16 + ((lane >> 4) << 3);
                LDSM4(ah2[mt], cvta(&sA[st][0][r][c]));
                LDSM4(al2[mt], cvta(&sA[st][1][r][c]));
            }
            int bg = lane >> 3;
            int kr = kp * 16 + ((bg & 1) << 3) + (lane & 7);
            int nc = wn * 16 + ((bg >> 1) << 3);
            LDSM4T(b0h, cvta(&sB0[st][0][kr][nc])); LDSM4T(b0l, cvta(&sB0[st][1][kr][nc]));
            LDSM4T(b1h, cvta(&sB1[st][0][kr][nc])); LDSM4T(b1l, cvta(&sB1[st][1][kr][nc]));
#pragma unroll
            for (int mt = 0; mt < 2; mt++)
#pragma unroll
                for (int nt = 0; nt < 2; nt++) {
                    MMA16(ag[mt][nt], ah2[mt], b0h[2 * nt], b0h[2 * nt + 1]);
                    MMA16(ag[mt][nt], ah2[mt], b0l[2 * nt], b0l[2 * nt + 1]);
                    MMA16(ag[mt][nt], al2[mt], b0h[2 * nt], b0h[2 * nt + 1]);
                    MMA16(au[mt][nt], ah2[mt], b1h[2 * nt], b1h[2 * nt + 1]);
                    MMA16(au[mt][nt], ah2[mt], b1l[2 * nt], b1l[2 * nt + 1]);
                    MMA16(au[mt][nt], al2[mt], b1h[2 * nt], b1h[2 * nt + 1]);
                }
        }
        __syncthreads();
    }
#pragma unroll
    for (int mt = 0; mt < 2; mt++)
#pragma unroll
        for (int nt = 0; nt < 2; nt++)
#pragma unroll
            for (int e = 0; e < 4; e++) {
                int r0 = bm + wm * 32 + mt * 16 + (lane >> 2) + (e >= 2 ? 8 : 0);
                int c0 = bn + wn * 16 + nt * 8 + 2 * (lane & 3) + (e & 1);
                float x = ag[mt][nt][e];
                float t = tanhf(0.7978845608028654f * (x + 0.044715f * x * x * x));
                splitstore(Oh, Ol, (size_t)r0 * N + c0, 0.5f * x * (1.f + t) * au[mt][nt][e]);
            }
}

// ============ flash attention: 64t tile x S, softcap, no-max softmax ============
__global__ void __launch_bounds__(256) k_flash(int is_local) {
    extern __shared__ char dsm[];
    bf16* sm = (bf16*)dsm;
    bf16 *sQh = sm, *sQl = sm + 4608, *sKh = sm + 2 * 4608, *sKl = sm + 3 * 4608,
         *sVh = sm + 4 * 4608, *sVl = sm + 5 * 4608, *sPh = sm + 6 * 4608, *sPl = sm + 7 * 4608;
    float* srs = (float*)(sm + 8 * 4608);
    int h = blockIdx.y, g = h / GSc, t0 = blockIdx.x * 64;
    int tid = threadIdx.x, lane = tid & 31, warp = tid >> 5;
    int wm = warp & 1, wn = warp >> 1;
    const bf16* Qh_ = bq_h + ((size_t)h * Tc + t0) * HDc;
    const bf16* Ql_ = bq_l + ((size_t)h * Tc + t0) * HDc;
#pragma unroll
    for (int i = 0; i < 2; i++) {
        int c = tid + i * 256, r = c >> 3, cc = (c & 7) << 3;
        CPA16(cvta(sQh + r * 72 + cc), Qh_ + r * HDc + cc);
        CPA16(cvta(sQl + r * 72 + cc), Ql_ + r * HDc + cc);
    }
    CPCOMMIT();
    if (tid < 64) srs[tid] = 0.f;
    float ao[2][2][4] = {};
    float rs_[2][2] = {};
    int s_lo = is_local ? ((CACHEc + t0 - WINc + 1) >> 6) : 0;
    int s_hi = (CACHEc + t0 + 63) >> 6;
    CPWAIT(0);
    __syncthreads();
    for (int stile = s_lo; stile <= s_hi; stile++) {
        int s0 = stile << 6;
        const bf16* Kh_ = bk_h + ((size_t)g * Sc + s0) * HDc;
        const bf16* Kl_ = bk_l + ((size_t)g * Sc + s0) * HDc;
        const bf16* Vh_ = bv_h + (size_t)g * HDc * Sc + s0;
        const bf16* Vl_ = bv_l + (size_t)g * HDc * Sc + s0;
#pragma unroll
        for (int i = 0; i < 2; i++) {
            int c = tid + i * 256, r = c >> 3, cc = (c & 7) << 3;
            CPA16(cvta(sKh + r * 72 + cc), Kh_ + r * HDc + cc);
            CPA16(cvta(sKl + r * 72 + cc), Kl_ + r * HDc + cc);
            CPA16(cvta(sVh + r * 72 + cc), Vh_ + (size_t)r * Sc + cc);
            CPA16(cvta(sVl + r * 72 + cc), Vl_ + (size_t)r * Sc + cc);
        }
        CPCOMMIT(); CPWAIT(0);
        __syncthreads();
        float sc_[2][2][4] = {};
#pragma unroll
        for (int kp = 0; kp < 4; kp++) {
            uint32_t ah2[2][4], al2[2][4], bh2[4], bl2[4];
#pragma unroll
            for (int mt = 0; mt < 2; mt++) {
                int r = wm * 32 + mt * 16 + (lane & 15), c = kp * 16 + ((lane >> 4) << 3);
                LDSM4(ah2[mt], cvta(sQh + r * 72 + c));
                LDSM4(al2[mt], cvta(sQl + r * 72 + c));
            }
            int bg = lane >> 3;
            int nr = wn * 16 + ((bg >> 1) << 3) + (lane & 7);
            int kc = kp * 16 + ((bg & 1) << 3);
            LDSM4(bh2, cvta(sKh + nr * 72 + kc));
            LDSM4(bl2, cvta(sKl + nr * 72 + kc));
#pragma unroll
            for (int mt = 0; mt < 2; mt++)
#pragma unroll
                for (int nt = 0; nt < 2; nt++) {
                    MMA16(sc_[mt][nt], ah2[mt], bh2[2 * nt], bh2[2 * nt + 1]);
                    MMA16(sc_[mt][nt], ah2[mt], bl2[2 * nt], bl2[2 * nt + 1]);
                    MMA16(sc_[mt][nt], al2[mt], bh2[2 * nt], bh2[2 * nt + 1]);
                }
        }
#pragma unroll
        for (int mt = 0; mt < 2; mt++)
#pragma unroll
            for (int nt = 0; nt < 2; nt++)
#pragma unroll
                for (int e = 0; e < 4; e++) {
                    int tl = wm * 32 + mt * 16 + (lane >> 2) + (e >= 2 ? 8 : 0);
                    int sl = wn * 16 + nt * 8 + 2 * (lane & 3) + (e & 1);
                    int sp = s0 + sl, qpos = CACHEc + t0 + tl;
                    float v = tanhf(sc_[mt][nt][e] * 0.0025f) * 50.f;
                    bool ok = (sp <= qpos) && (!is_local || sp > qpos - WINc);
                    float p = ok ? __expf(v) : 0.f;
                    rs_[mt][e >= 2 ? 1 : 0] += p;
                    bf16 ph = __float2bfloat16(p);
                    sPh[tl * 72 + sl] = ph;
                    sPl[tl * 72 + sl] = __float2bfloat16(p - __bfloat162float(ph));
                }
        __syncthreads();
#pragma unroll
        for (int kp = 0; kp < 4; kp++) {
            uint32_t ah2[2][4], al2[2][4], bh2[4], bl2[4];
#pragma unroll
            for (int mt = 0; mt < 2; mt++) {
                int r = wm * 32 + mt * 16 + (lane & 15), c = kp * 16 + ((lane >> 4) << 3);
                LDSM4(ah2[mt], cvta(sPh + r * 72 + c));
                LDSM4(al2[mt], cvta(sPl + r * 72 + c));
            }
            int bg = lane >> 3;
            int nr = wn * 16 + ((bg >> 1) << 3) + (lane & 7);
            int kc = kp * 16 + ((bg & 1) << 3);
            LDSM4(bh2, cvta(sVh + nr * 72 + kc));
            LDSM4(bl2, cvta(sVl + nr * 72 + kc));
#pragma unroll
            for (int mt = 0; mt < 2; mt++)
#pragma unroll
                for (int nt = 0; nt < 2; nt++) {
                    MMA16(ao[mt][nt], ah2[mt], bh2[2 * nt], bh2[2 * nt + 1]);
                    MMA16(ao[mt][nt], ah2[mt], bl2[2 * nt], bl2[2 * nt + 1]);
                    MMA16(ao[mt][nt], al2[mt], bh2[2 * nt], bh2[2 * nt + 1]);
                }
        }
        __syncthreads();
    }
#pragma unroll
    for (int mt = 0; mt < 2; mt++) {
        atomicAdd(&srs[wm * 32 + mt * 16 + (lane >> 2)], rs_[mt][0]);
        atomicAdd(&srs[wm * 32 + mt * 16 + (lane >> 2) + 8], rs_[mt][1]);
    }
    __syncthreads();
#pragma unroll
    for (int mt = 0; mt < 2; mt++)
#pragma unroll
        for (int nt = 0; nt < 2; nt++) {
            int tl = wm * 32 + mt * 16 + (lane >> 2);
            int d = wn * 16 + nt * 8 + 2 * (lane & 3);
            float i0 = 1.f / srs[tl], i1 = 1.f / srs[tl + 8];
            size_t b0 = (size_t)(t0 + tl) * Dc + h * HDc + d;
            size_t b1 = (size_t)(t0 + tl + 8) * Dc + h * HDc + d;
            splitstore(bat_h, bat_l, b0, ao[mt][nt][0] * i0);
            splitstore(bat_h, bat_l, b0 + 1, ao[mt][nt][1] * i0);
            splitstore(bat_h, bat_l, b1, ao[mt][nt][2] * i1);
            splitstore(bat_h, bat_l, b1 + 1, ao[mt][nt][3] * i1);
        }
}

// ---------------- host ----------------
extern "C" void kernel_launch(void* const* d_in, const int* in_sizes, int n_in,
                              void* d_out, int out_size) {
    const float *emb = 0, *kvk = 0, *kvv = 0, *pre_attn = 0, *wqkv = 0, *qnorm = 0,
                *knorm = 0, *wout = 0, *post_attn = 0, *pre_ff = 0, *wgate = 0,
                *wup = 0, *wdown = 0, *post_ff = 0, *finalw = 0, *wlm = 0,
                *cosg = 0, *sing = 0, *cosl = 0, *sinl = 0;
    int kv_n = 0, a = 0, b = 0, c = 0, d = 0;
    for (int i = 0; i < n_in; i++) {
        const float* p = (const float*)d_in[i];
        int s = in_sizes[i];
        if (s == 393216) emb = p;
        else if (s == 10223616) { if (kv_n++ == 0) kvk = p; else kvv = p; }
        else if (s == 19968) { if (a == 0) pre_attn = p; else if (a == 1) post_attn = p; else if (a == 2) pre_ff = p; else post_ff = p; a++; }
        else if (s == SZ_WQKV) wqkv = p;
        else if (s == 1664) { if (b++ == 0) qnorm = p; else knorm = p; }
        else if (s == SZ_WOUT) wout = p;
        else if (s == SZ_WFF) { if (c == 0) wgate = p; else if (c == 1) wup = p; else wdown = p; c++; }
        else if (s == 768) finalw = p;
        else if (s == SZ_WLM) wlm = p;
        else if (s == 32768) { if (d == 0) cosg = p; else if (d == 1) sing = p; else if (d == 2) cosl = p; else sinl = p; d++; }
    }
    float *ph, *pqkv, *pt1;
    bf16 *pxh, *pxl, *path, *patl, *pgh, *pgl, *kh, *kl, *vh, *vl;
    bf16 *qkvh, *qkvl, *outh, *outl, *dnh, *dnl, *lmh, *lml, *gth, *gtl, *uph, *upl;
    cudaGetSymbolAddress((void**)&ph, g_h);
    cudaGetSymbolAddress((void**)&pqkv, g_qkv);
    cudaGetSymbolAddress((void**)&pt1, g_t1);
    cudaGetSymbolAddress((void**)&pxh, bx_h); cudaGetSymbolAddress((void**)&pxl, bx_l);
    cudaGetSymbolAddress((void**)&path, bat_h); cudaGetSymbolAddress((void**)&patl, bat_l);
    cudaGetSymbolAddress((void**)&pgh, bgt_h); cudaGetSymbolAddress((void**)&pgl, bgt_l);
    cudaGetSymbolAddress((void**)&kh, bk_h); cudaGetSymbolAddress((void**)&kl, bk_l);
    cudaGetSymbolAddress((void**)&vh, bv_h); cudaGetSymbolAddress((void**)&vl, bv_l);
    cudaGetSymbolAddress((void**)&qkvh, wqkv_h); cudaGetSymbolAddress((void**)&qkvl, wqkv_l);
    cudaGetSymbolAddress((void**)&outh, wout_h); cudaGetSymbolAddress((void**)&outl, wout_l);
    cudaGetSymbolAddress((void**)&gth, wgt_h); cudaGetSymbolAddress((void**)&gtl, wgt_l);
    cudaGetSymbolAddress((void**)&uph, wup_h); cudaGetSymbolAddress((void**)&upl, wup_l);
    cudaGetSymbolAddress((void**)&dnh, wdn_h); cudaGetSymbolAddress((void**)&dnl, wdn_l);
    cudaGetSymbolAddress((void**)&lmh, wlm_h); cudaGetSymbolAddress((void**)&lml, wlm_l);

    cudaFuncSetAttribute(k_flash, cudaFuncAttributeMaxDynamicSharedMemorySize, 74 * 1024);
    cudaFuncSetAttribute(k_mmff, cudaFuncAttributeMaxDynamicSharedMemorySize, 58 * 1024);

    k_split4<<<SZ_WQKV / 4 / 256, 256>>>(wqkv, qkvh, qkvl, SZ_WQKV / 4);
    k_split4<<<SZ_WOUT / 4 / 256, 256>>>(wout, outh, outl, SZ_WOUT / 4);
    k_split4<<<SZ_WFF / 4 / 256, 256>>>(wgate, gth, gtl, SZ_WFF / 4);
    k_split4<<<SZ_WFF / 4 / 256, 256>>>(wup, uph, upl, SZ_WFF / 4);
    k_split4<<<SZ_WFF / 4 / 256, 256>>>(wdown, dnh, dnl, SZ_WFF / 4);
    k_split4<<<SZ_WLM / 4 / 256, 256>>>(wlm, lmh, lml, SZ_WLM / 4);

    k_init<<<Tc, 256>>>(emb, pre_attn, ph, pxh, pxl);

    for (int i = 0; i < Lc; i++) {
        int is_local = ((i + 1) % 6 == 0) ? 1 : 0;
        const float* cs = is_local ? cosl : cosg;
        const float* sn = is_local ? sinl : sing;
        k_convkv<<<768, 256>>>(kvk + (size_t)i * 393216, kvv + (size_t)i * 393216,
                               kh, kl, vh, vl);
        k_mm<<<dim3(QKVW / 64, Tc / 64), 256>>>(pxh, pxl, qkvh + (size_t)i * Dc * QKVW,
                                                qkvl + (size_t)i * Dc * QKVW, pqkv, QKVW, Dc);
        k_qkprep<<<dim3(Tc, NGc), HDc>>>(pqkv, qnorm + i * HDc, knorm + i * HDc, cs, sn);
        k_flash<<<dim3(Tc / 64, NHc), 256, 74 * 1024>>>(is_local);
        k_mm<<<dim3(Dc / 64, Tc / 64), 256>>>(path, patl, outh + (size_t)i * Dc * Dc,
                                              outl + (size_t)i * Dc * Dc, pt1, Dc, Dc);
        k_fuse<<<Tc, 256>>>(ph, pt1, post_attn + i * Dc, pre_ff + i * Dc, pxh, pxl);
        k_mmff<<<dim3(FFc / 64, Tc / 64), 256, 58 * 1024>>>(
            pxh, pxl,
            gth + (size_t)i * Dc * FFc, gtl + (size_t)i * Dc * FFc,
            uph + (size_t)i * Dc * FFc, upl + (size_t)i * Dc * FFc,
            pgh, pgl);
        k_mm<<<dim3(Dc / 64, Tc / 64), 256>>>(pgh, pgl, dnh + (size_t)i * FFc * Dc,
                                              dnl + (size_t)i * FFc * Dc, pt1, Dc, FFc);
        const float* wpre = (i + 1 < Lc) ? pre_attn + (i + 1) * Dc : finalw;
        k_fuse<<<Tc, 256>>>(ph, pt1, post_ff + i * Dc, wpre, pxh, pxl);
    }
    k_mm<<<dim3(Vocab / 64, Tc / 64), 256>>>(pxh, pxl, lmh, lml, (float*)d_out, Vocab, Dc);
}